// round 1
// baseline (speedup 1.0000x reference)
#include <cuda_runtime.h>
#include <math.h>

#define D        128
#define N_NODES  5000
#define WINDOW   10
#define N_TOTAL  (WINDOW * N_NODES)   // 50000
#define NE       131072
#define HID      1024
#define TEDGE    (N_TOTAL - N_NODES)  // 45000 forward temporal edges
#define TE2      (2 * TEDGE)          // 90000 total temporal edges

// ---------------- device scratch (static, allocation-free) ----------------
__device__ float g_h[N_TOTAL * D];
__device__ float g_hidden[(size_t)NE * HID];   // 536 MB, reused for temporal stage
__device__ float g_m[NE * D];                  // edge messages (also temporal msgs)
__device__ float g_agg[N_TOTAL * D];
__device__ float g_xg[N_TOTAL * 3 * D];
__device__ float g_hg[N_TOTAL * 3 * D];
__device__ int   g_cnt[N_TOTAL];
__device__ int   g_nidx[NE];
__device__ int   g_midx[NE];
__device__ float g_x1[N_NODES * HID];
__device__ float g_x2[N_NODES * 512];

// ---------------- generic tiled SGEMM ----------------
// C[M,N] = act( A' @ B + bias ),  B row-major KxN, N % 128 == 0, K % 16 == 0.
// MODE 0: A' = A (row-major MxK)
// MODE 1: A'[r,k] = g_h[ (k<128 ? idxA[r] : idxB[r])*128 + (k&127) ]   (K=256)
// MODE 2: same concat-gather with analytic temporal indices             (K=256)
#define BM 128
#define BN 128
#define BK 16

template<int MODE, int RELU>
__global__ __launch_bounds__(256)
void sgemm_kernel(const float* __restrict__ A,
                  const float* __restrict__ B,
                  const float* __restrict__ bias,
                  float* __restrict__ C,
                  int M, int N, int K,
                  const int* __restrict__ idxA,
                  const int* __restrict__ idxB)
{
    __shared__ float As[BK][BM];
    __shared__ float Bs[BK][BN];

    const int tid = threadIdx.x;
    const int tx = tid & 15;
    const int ty = tid >> 4;
    const int n0 = blockIdx.x * BN;
    const int m0 = blockIdx.y * BM;

    float acc[8][8];
#pragma unroll
    for (int i = 0; i < 8; ++i)
#pragma unroll
        for (int j = 0; j < 8; ++j) acc[i][j] = 0.f;

    const int kTiles = K / BK;
    for (int kt = 0; kt < kTiles; ++kt) {
        const int k0 = kt * BK;
        // ---- load A tile (128 rows x 16 cols) ----
#pragma unroll
        for (int l = 0; l < 2; ++l) {
            const int row = (tid >> 2) + l * 64;   // 0..127
            const int kv  = tid & 3;               // float4 index within BK
            const int gRow = m0 + row;
            float4 v = make_float4(0.f, 0.f, 0.f, 0.f);
            if (gRow < M) {
                const int kg = k0 + kv * 4;
                if (MODE == 0) {
                    v = *(const float4*)(A + (size_t)gRow * K + kg);
                } else {
                    int src;
                    if (MODE == 1) {
                        src = (kg < D) ? idxA[gRow] : idxB[gRow];
                    } else {
                        int sA, sB;
                        if (gRow < TEDGE) { sA = gRow;                  sB = gRow + N_NODES; }
                        else              { sA = gRow - TEDGE + N_NODES; sB = gRow - TEDGE;  }
                        src = (kg < D) ? sA : sB;
                    }
                    v = *(const float4*)(g_h + (size_t)src * D + (kg & (D - 1)));
                }
            }
            As[kv * 4 + 0][row] = v.x;
            As[kv * 4 + 1][row] = v.y;
            As[kv * 4 + 2][row] = v.z;
            As[kv * 4 + 3][row] = v.w;
        }
        // ---- load B tile (16 rows x 128 cols) ----
#pragma unroll
        for (int l = 0; l < 2; ++l) {
            const int nv = tx + l * 16;            // 0..31
            float4 v = *(const float4*)(B + (size_t)(k0 + ty) * N + n0 + nv * 4);
            *(float4*)&Bs[ty][nv * 4] = v;
        }
        __syncthreads();
        // ---- compute ----
#pragma unroll
        for (int kk = 0; kk < BK; ++kk) {
            float4 a0 = *(const float4*)&As[kk][ty * 8];
            float4 a1 = *(const float4*)&As[kk][ty * 8 + 4];
            float4 b0 = *(const float4*)&Bs[kk][tx * 8];
            float4 b1 = *(const float4*)&Bs[kk][tx * 8 + 4];
            float a[8] = {a0.x, a0.y, a0.z, a0.w, a1.x, a1.y, a1.z, a1.w};
            float b[8] = {b0.x, b0.y, b0.z, b0.w, b1.x, b1.y, b1.z, b1.w};
#pragma unroll
            for (int i = 0; i < 8; ++i)
#pragma unroll
                for (int j = 0; j < 8; ++j)
                    acc[i][j] = fmaf(a[i], b[j], acc[i][j]);
        }
        __syncthreads();
    }
    // ---- epilogue ----
#pragma unroll
    for (int i = 0; i < 8; ++i) {
        const int gRow = m0 + ty * 8 + i;
        if (gRow >= M) break;
#pragma unroll
        for (int j = 0; j < 8; j += 4) {
            const int col = n0 + tx * 8 + j;
            float4 o;
            o.x = acc[i][j + 0] + bias[col + 0];
            o.y = acc[i][j + 1] + bias[col + 1];
            o.z = acc[i][j + 2] + bias[col + 2];
            o.w = acc[i][j + 3] + bias[col + 3];
            if (RELU) {
                o.x = fmaxf(o.x, 0.f); o.y = fmaxf(o.y, 0.f);
                o.z = fmaxf(o.z, 0.f); o.w = fmaxf(o.w, 0.f);
            }
            *(float4*)(C + (size_t)gRow * N + col) = o;
        }
    }
}

// ---------------- small kernels ----------------
__global__ void init_h_kernel(const int* __restrict__ nodes,
                              const float* __restrict__ embed)
{
    int i = blockIdx.x * blockDim.x + threadIdx.x;
    if (i >= N_TOTAL * D) return;
    int row = i >> 7, c = i & 127;
    g_h[i] = embed[nodes[row / WINDOW] * D + c];
}

__global__ void edge_idx_kernel(const int* __restrict__ ie)
{
    int e = blockIdx.x * blockDim.x + threadIdx.x;
    if (e >= NE) return;
    int t = ie[e * 3 + 0], s = ie[e * 3 + 1], d2 = ie[e * 3 + 2];
    g_nidx[e] = t * N_NODES + s;
    g_midx[e] = t * N_NODES + d2;
}

__global__ void zero_cnt_kernel()
{
    int i = blockIdx.x * blockDim.x + threadIdx.x;
    if (i < N_TOTAL) g_cnt[i] = 0;
}

__global__ void count_kernel()
{
    int e = blockIdx.x * blockDim.x + threadIdx.x;
    if (e < NE) atomicAdd(&g_cnt[g_midx[e]], 1);
}

__global__ void zero_agg_kernel()
{
    int i = blockIdx.x * blockDim.x + threadIdx.x;
    if (i < N_TOTAL * D) g_agg[i] = 0.f;
}

__global__ void scatter_kernel()
{
    int i = blockIdx.x * blockDim.x + threadIdx.x;
    if (i >= NE * D) return;
    int e = i >> 7, c = i & 127;
    atomicAdd(&g_agg[g_midx[e] * D + c], g_m[i]);
}

__global__ void mean_kernel()
{
    int i = blockIdx.x * blockDim.x + threadIdx.x;
    if (i >= N_TOTAL * D) return;
    int r = i >> 7;
    int c = g_cnt[r];
    g_agg[i] = (c > 0) ? g_agg[i] / (float)c : 0.f;
}

__global__ void temp_agg_kernel()
{
    int i = blockIdx.x * blockDim.x + threadIdx.x;
    if (i >= N_TOTAL * D) return;
    int v = i >> 7, c = i & 127;
    float s = 0.f; int n = 0;
    if (v >= N_NODES) { s += g_m[(v - N_NODES) * D + c]; n++; }  // fwd edge dst=v
    if (v < TEDGE)    { s += g_m[(TEDGE + v) * D + c];   n++; }  // bwd edge dst=v
    g_agg[i] = s / (float)n;
}

__device__ __forceinline__ float sigmoidf(float x) { return 1.f / (1.f + expf(-x)); }

__global__ void gru_kernel()
{
    int i = blockIdx.x * blockDim.x + threadIdx.x;
    if (i >= N_TOTAL * D) return;
    int r = i >> 7, c = i & 127;
    const float* xg = g_xg + (size_t)r * 384;
    const float* hg = g_hg + (size_t)r * 384;
    float z  = sigmoidf(xg[c]       + hg[c]);
    float rr = sigmoidf(xg[128 + c] + hg[128 + c]);
    float hc = tanhf(xg[256 + c] + rr * hg[256 + c]);
    float h = g_h[i];
    g_h[i] = z * h + (1.f - z) * hc;
}

__global__ void logits_softmax_kernel(const float* __restrict__ W3,
                                      const float* __restrict__ b3,
                                      float* __restrict__ out)
{
    const int row = blockIdx.x;
    const int w = threadIdx.x >> 5, lane = threadIdx.x & 31;
    __shared__ float lg[10];
    float s = 0.f;
    for (int k = lane; k < 512; k += 32)
        s += g_x2[(size_t)row * 512 + k] * W3[k * 10 + w];
#pragma unroll
    for (int o = 16; o; o >>= 1) s += __shfl_down_sync(0xffffffff, s, o);
    if (lane == 0) lg[w] = s + b3[w];
    __syncthreads();
    if (threadIdx.x == 0) {
        float mx = lg[0];
#pragma unroll
        for (int c = 1; c < 10; ++c) mx = fmaxf(mx, lg[c]);
        float e[10], sum = 0.f;
#pragma unroll
        for (int c = 0; c < 10; ++c) { e[c] = expf(lg[c] - mx); sum += e[c]; }
#pragma unroll
        for (int c = 0; c < 10; ++c) out[row * 10 + c] = e[c] / sum;
    }
}

// ---------------- host orchestration ----------------
static inline void run_sgemm(int mode, int relu,
                             const float* A, const float* B, const float* bias,
                             float* C, int M, int N, int K,
                             const int* idxA, const int* idxB)
{
    dim3 grid(N / BN, (M + BM - 1) / BM);
    dim3 block(256);
    if (mode == 0) {
        if (relu) sgemm_kernel<0,1><<<grid, block>>>(A, B, bias, C, M, N, K, idxA, idxB);
        else      sgemm_kernel<0,0><<<grid, block>>>(A, B, bias, C, M, N, K, idxA, idxB);
    } else if (mode == 1) {
        if (relu) sgemm_kernel<1,1><<<grid, block>>>(A, B, bias, C, M, N, K, idxA, idxB);
        else      sgemm_kernel<1,0><<<grid, block>>>(A, B, bias, C, M, N, K, idxA, idxB);
    } else {
        if (relu) sgemm_kernel<2,1><<<grid, block>>>(A, B, bias, C, M, N, K, idxA, idxB);
        else      sgemm_kernel<2,0><<<grid, block>>>(A, B, bias, C, M, N, K, idxA, idxB);
    }
}

extern "C" void kernel_launch(void* const* d_in, const int* in_sizes, int n_in,
                              void* d_out, int out_size)
{
    const int*   ie        = (const int*)  d_in[0];
    const int*   nodes     = (const int*)  d_in[1];
    const float* embed     = (const float*)d_in[2];
    const float* msg_W1    = (const float*)d_in[3];
    const float* msg_b1    = (const float*)d_in[4];
    const float* msg_W2    = (const float*)d_in[5];
    const float* msg_b2    = (const float*)d_in[6];
    const float* gru_int_W = (const float*)d_in[7];
    const float* gru_int_U = (const float*)d_in[8];
    const float* gru_int_b = (const float*)d_in[9];
    const float* gru_tmp_W = (const float*)d_in[10];
    const float* gru_tmp_U = (const float*)d_in[11];
    const float* gru_tmp_b = (const float*)d_in[12];
    const float* ro_W1     = (const float*)d_in[13];
    const float* ro_b1     = (const float*)d_in[14];
    const float* ro_W2     = (const float*)d_in[15];
    const float* ro_b2     = (const float*)d_in[16];
    const float* ro_W3     = (const float*)d_in[17];
    const float* ro_b3     = (const float*)d_in[18];
    float* out = (float*)d_out;

    float *h_p, *hid_p, *m_p, *agg_p, *xg_p, *hg_p, *x1_p, *x2_p;
    int *nidx_p, *midx_p;
    cudaGetSymbolAddress((void**)&h_p,   g_h);
    cudaGetSymbolAddress((void**)&hid_p, g_hidden);
    cudaGetSymbolAddress((void**)&m_p,   g_m);
    cudaGetSymbolAddress((void**)&agg_p, g_agg);
    cudaGetSymbolAddress((void**)&xg_p,  g_xg);
    cudaGetSymbolAddress((void**)&hg_p,  g_hg);
    cudaGetSymbolAddress((void**)&x1_p,  g_x1);
    cudaGetSymbolAddress((void**)&x2_p,  g_x2);
    cudaGetSymbolAddress((void**)&nidx_p, g_nidx);
    cudaGetSymbolAddress((void**)&midx_p, g_midx);

    const int EL = 256;
    init_h_kernel<<<(N_TOTAL * D + EL - 1) / EL, EL>>>(nodes, embed);
    edge_idx_kernel<<<(NE + EL - 1) / EL, EL>>>(ie);
    zero_cnt_kernel<<<(N_TOTAL + EL - 1) / EL, EL>>>();
    count_kernel<<<(NE + EL - 1) / EL, EL>>>();

    for (int t = 0; t < 2; ++t) {
        // ---- interaction stage ----
        run_sgemm(1, 1, nullptr, msg_W1, msg_b1, hid_p, NE, HID, 2 * D, nidx_p, midx_p);
        run_sgemm(0, 1, hid_p, msg_W2, msg_b2, m_p, NE, D, HID, nullptr, nullptr);
        zero_agg_kernel<<<(N_TOTAL * D + EL - 1) / EL, EL>>>();
        scatter_kernel<<<(NE * D + EL - 1) / EL, EL>>>();
        mean_kernel<<<(N_TOTAL * D + EL - 1) / EL, EL>>>();
        run_sgemm(0, 0, agg_p, gru_int_W, gru_int_b,       xg_p, N_TOTAL, 3 * D, D, nullptr, nullptr);
        run_sgemm(0, 0, h_p,   gru_int_U, gru_int_b + 384, hg_p, N_TOTAL, 3 * D, D, nullptr, nullptr);
        gru_kernel<<<(N_TOTAL * D + EL - 1) / EL, EL>>>();

        // ---- temporal stage (analytic edges) ----
        run_sgemm(2, 1, nullptr, msg_W1, msg_b1, hid_p, TE2, HID, 2 * D, nullptr, nullptr);
        run_sgemm(0, 1, hid_p, msg_W2, msg_b2, m_p, TE2, D, HID, nullptr, nullptr);
        temp_agg_kernel<<<(N_TOTAL * D + EL - 1) / EL, EL>>>();
        run_sgemm(0, 0, agg_p, gru_tmp_W, gru_tmp_b,       xg_p, N_TOTAL, 3 * D, D, nullptr, nullptr);
        run_sgemm(0, 0, h_p,   gru_tmp_U, gru_tmp_b + 384, hg_p, N_TOTAL, 3 * D, D, nullptr, nullptr);
        gru_kernel<<<(N_TOTAL * D + EL - 1) / EL, EL>>>();
    }

    // ---- readout ----
    run_sgemm(0, 1, h_p,  ro_W1, ro_b1, x1_p, N_NODES, HID, D,   nullptr, nullptr);
    run_sgemm(0, 1, x1_p, ro_W2, ro_b2, x2_p, N_NODES, 512, HID, nullptr, nullptr);
    logits_softmax_kernel<<<N_NODES, 320>>>(ro_W3, ro_b3, out);
}

// round 3
// speedup vs baseline: 1.5372x; 1.5372x over previous
#include <cuda_runtime.h>
#include <cuda_bf16.h>
#include <math.h>
#include <stdint.h>

#define D        128
#define N_NODES  5000
#define WINDOW   10
#define N_TOTAL  50000
#define NE       131072
#define HID      1024
#define TEDGE    45000
#define TE2      90000

// ---------------- device scratch (static, allocation-free) ----------------
__device__ __align__(16) float g_h[N_TOTAL * D];
__device__ __align__(16) float g_m[NE * D];
__device__ __align__(16) float g_agg[N_TOTAL * D];
__device__ __align__(16) float g_xg[N_TOTAL * 3 * D];
__device__ __align__(16) float g_hg[N_TOTAL * 3 * D];
__device__ int   g_cnt[N_TOTAL];
__device__ int   g_nidx[NE];
__device__ int   g_midx[NE];
__device__ __align__(16) float g_x2[N_NODES * 512];

// hidden activations, split hi/lo bf16 (msg MLP and readout reuse)
__device__ __align__(16) __nv_bfloat16 g_hid_hi[(size_t)NE * HID];
__device__ __align__(16) __nv_bfloat16 g_hid_lo[(size_t)NE * HID];

// transposed + split weights, layout [N][K] (K contiguous)
__device__ __align__(16) __nv_bfloat16 g_W1t_hi[HID * 256], g_W1t_lo[HID * 256];
__device__ __align__(16) __nv_bfloat16 g_W2t_hi[D * HID],   g_W2t_lo[D * HID];
__device__ __align__(16) __nv_bfloat16 g_GiW_hi[384 * D],   g_GiW_lo[384 * D];
__device__ __align__(16) __nv_bfloat16 g_GiU_hi[384 * D],   g_GiU_lo[384 * D];
__device__ __align__(16) __nv_bfloat16 g_GtW_hi[384 * D],   g_GtW_lo[384 * D];
__device__ __align__(16) __nv_bfloat16 g_GtU_hi[384 * D],   g_GtU_lo[384 * D];
__device__ __align__(16) __nv_bfloat16 g_R1t_hi[HID * D],   g_R1t_lo[HID * D];
__device__ __align__(16) __nv_bfloat16 g_R2t_hi[512 * HID], g_R2t_lo[512 * HID];

// ---------------- helpers ----------------
__device__ __forceinline__ uint32_t smem_u32(const void* p) {
    uint32_t a;
    asm("{ .reg .u64 t; cvta.to.shared.u64 t, %1; cvt.u32.u64 %0, t; }" : "=r"(a) : "l"(p));
    return a;
}

__device__ __forceinline__ void ldsm4(uint32_t& r0, uint32_t& r1, uint32_t& r2, uint32_t& r3, uint32_t addr) {
    asm volatile("ldmatrix.sync.aligned.m8n8.x4.shared.b16 {%0,%1,%2,%3}, [%4];"
                 : "=r"(r0), "=r"(r1), "=r"(r2), "=r"(r3) : "r"(addr));
}

__device__ __forceinline__ void mma16816(float* c, const uint32_t* a, const uint32_t* b) {
    asm volatile("mma.sync.aligned.m16n8k16.row.col.f32.bf16.bf16.f32 "
                 "{%0,%1,%2,%3}, {%4,%5,%6,%7}, {%8,%9}, {%0,%1,%2,%3};"
                 : "+f"(c[0]), "+f"(c[1]), "+f"(c[2]), "+f"(c[3])
                 : "r"(a[0]), "r"(a[1]), "r"(a[2]), "r"(a[3]), "r"(b[0]), "r"(b[1]));
}

__device__ __forceinline__ void split2(float x, float y, uint32_t& h, uint32_t& l) {
    __nv_bfloat16 hx = __float2bfloat16(x);
    __nv_bfloat16 hy = __float2bfloat16(y);
    __nv_bfloat16 lx = __float2bfloat16(x - __bfloat162float(hx));
    __nv_bfloat16 ly = __float2bfloat16(y - __bfloat162float(hy));
    h = ((uint32_t)__bfloat16_as_ushort(hy) << 16) | (uint32_t)__bfloat16_as_ushort(hx);
    l = ((uint32_t)__bfloat16_as_ushort(ly) << 16) | (uint32_t)__bfloat16_as_ushort(lx);
}

// ---------------- HMMA split-bf16 GEMM ----------------
// C[M, Ncols] = act( A'[M,K] @ W[K,Ncols] + bias ), CTA tile 128x128, Kstep 32.
// B given pre-split/transposed: Bhi/Blo layout [N][K] (== col-major B).
// AMODE 0: A fp32 row-major (split on load)
// AMODE 1: A = concat(g_h[idxA[r]], g_h[idxB[r]]) fp32, K=256
// AMODE 2: same with analytic temporal indices, K=256
// AMODE 3: A pre-split bf16 hi/lo, row-major stride lda
// OUTSPLIT 0: fp32 to Cf(ldc). OUTSPLIT 1: bf16 hi/lo to Chi/Clo(ldc).
#define ASTR   56                        // bf16 elems per smem row (112 B)
#define PANEL  (128 * ASTR)              // elems per panel
#define SMEM_BYTES (4 * PANEL * 2)       // 57344

template<int AMODE, int OUTSPLIT, int RELU>
__global__ __launch_bounds__(256, 1)
void hmma_gemm(const float* __restrict__ Af,
               const __nv_bfloat16* __restrict__ Ahi_g,
               const __nv_bfloat16* __restrict__ Alo_g,
               int lda,
               const int* __restrict__ idxA, const int* __restrict__ idxB,
               const __nv_bfloat16* __restrict__ Bhi, const __nv_bfloat16* __restrict__ Blo,
               const float* __restrict__ bias,
               float* __restrict__ Cf,
               __nv_bfloat16* __restrict__ Chi, __nv_bfloat16* __restrict__ Clo,
               int ldc, int M, int K)
{
    extern __shared__ __nv_bfloat16 smbuf[];
    __nv_bfloat16* sAhi = smbuf;
    __nv_bfloat16* sAlo = sAhi + PANEL;
    __nv_bfloat16* sBhi = sAlo + PANEL;
    __nv_bfloat16* sBlo = sBhi + PANEL;
    const uint32_t sbase = smem_u32(smbuf);
    const uint32_t OFF_ALO = PANEL * 2;
    const uint32_t OFF_BHI = 2 * PANEL * 2;
    const uint32_t OFF_BLO = 3 * PANEL * 2;

    const int t = threadIdx.x, lane = t & 31, w = t >> 5;
    const int wm = w >> 2, wn = w & 3;           // warp grid 2(M) x 4(N)
    const int m0 = blockIdx.y * 128, n0 = blockIdx.x * 128;

    float acc[4][4][4];
#pragma unroll
    for (int i = 0; i < 4; ++i)
#pragma unroll
        for (int j = 0; j < 4; ++j)
#pragma unroll
            for (int q = 0; q < 4; ++q) acc[i][j][q] = 0.f;

    const int lrow = t >> 1;        // 0..127
    const int lhalf = t & 1;        // 0/1 -> 16-elem half

    const int steps = K >> 5;
    for (int s = 0; s < steps; ++s) {
        const int k0 = s << 5;
        // ---- load A panel (128 x 32) hi/lo ----
        {
            int gRow = m0 + lrow; if (gRow >= M) gRow = M - 1;
            __nv_bfloat16* dh = sAhi + lrow * ASTR + lhalf * 16;
            __nv_bfloat16* dl = sAlo + lrow * ASTR + lhalf * 16;
            if (AMODE == 3) {
                const size_t off = (size_t)gRow * lda + k0 + lhalf * 16;
                *(uint4*)dh       = *(const uint4*)(Ahi_g + off);
                *(uint4*)(dh + 8) = *(const uint4*)(Ahi_g + off + 8);
                *(uint4*)dl       = *(const uint4*)(Alo_g + off);
                *(uint4*)(dl + 8) = *(const uint4*)(Alo_g + off + 8);
            } else {
                const float* src;
                if (AMODE == 0) {
                    src = Af + (size_t)gRow * lda + k0 + lhalf * 16;
                } else {
                    int sidx;
                    if (AMODE == 1) {
                        sidx = (k0 < 128) ? idxA[gRow] : idxB[gRow];
                    } else {
                        int sA_, sB_;
                        if (gRow < TEDGE) { sA_ = gRow;                   sB_ = gRow + N_NODES; }
                        else              { sA_ = gRow - TEDGE + N_NODES; sB_ = gRow - TEDGE;   }
                        sidx = (k0 < 128) ? sA_ : sB_;
                    }
                    src = g_h + (size_t)sidx * 128 + (k0 & 127) + lhalf * 16;
                }
                float4 v0 = *(const float4*)(src);
                float4 v1 = *(const float4*)(src + 4);
                float4 v2 = *(const float4*)(src + 8);
                float4 v3 = *(const float4*)(src + 12);
                uint32_t h[8], l[8];
                split2(v0.x, v0.y, h[0], l[0]); split2(v0.z, v0.w, h[1], l[1]);
                split2(v1.x, v1.y, h[2], l[2]); split2(v1.z, v1.w, h[3], l[3]);
                split2(v2.x, v2.y, h[4], l[4]); split2(v2.z, v2.w, h[5], l[5]);
                split2(v3.x, v3.y, h[6], l[6]); split2(v3.z, v3.w, h[7], l[7]);
                *(uint4*)dh       = make_uint4(h[0], h[1], h[2], h[3]);
                *(uint4*)(dh + 8) = make_uint4(h[4], h[5], h[6], h[7]);
                *(uint4*)dl       = make_uint4(l[0], l[1], l[2], l[3]);
                *(uint4*)(dl + 8) = make_uint4(l[4], l[5], l[6], l[7]);
            }
        }
        // ---- load B panel (128 n-rows x 32 k) hi/lo ----
        {
            const size_t off = (size_t)(n0 + lrow) * K + k0 + lhalf * 16;
            __nv_bfloat16* dh = sBhi + lrow * ASTR + lhalf * 16;
            __nv_bfloat16* dl = sBlo + lrow * ASTR + lhalf * 16;
            *(uint4*)dh       = *(const uint4*)(Bhi + off);
            *(uint4*)(dh + 8) = *(const uint4*)(Bhi + off + 8);
            *(uint4*)dl       = *(const uint4*)(Blo + off);
            *(uint4*)(dl + 8) = *(const uint4*)(Blo + off + 8);
        }
        __syncthreads();

        // ---- compute: two k16 slices ----
#pragma unroll
        for (int kk = 0; kk < 2; ++kk) {
            const int kc = kk * 16;
            uint32_t ah[4][4], al[4][4];
#pragma unroll
            for (int mt = 0; mt < 4; ++mt) {
                const uint32_t aoff =
                    ((uint32_t)((wm * 64 + mt * 16 + (lane & 15)) * ASTR + kc + ((lane >> 4) << 3))) << 1;
                ldsm4(ah[mt][0], ah[mt][1], ah[mt][2], ah[mt][3], sbase + aoff);
                ldsm4(al[mt][0], al[mt][1], al[mt][2], al[mt][3], sbase + OFF_ALO + aoff);
            }
            uint32_t bh[4][2], bl[4][2];
#pragma unroll
            for (int p = 0; p < 2; ++p) {
                const uint32_t boff =
                    ((uint32_t)((wn * 32 + p * 16 + ((lane >> 4) << 3) + (lane & 7)) * ASTR
                                + kc + (((lane >> 3) & 1) << 3))) << 1;
                uint32_t r0, r1, r2, r3;
                ldsm4(r0, r1, r2, r3, sbase + OFF_BHI + boff);
                bh[p * 2][0] = r0; bh[p * 2][1] = r1; bh[p * 2 + 1][0] = r2; bh[p * 2 + 1][1] = r3;
                ldsm4(r0, r1, r2, r3, sbase + OFF_BLO + boff);
                bl[p * 2][0] = r0; bl[p * 2][1] = r1; bl[p * 2 + 1][0] = r2; bl[p * 2 + 1][1] = r3;
            }
#pragma unroll
            for (int mt = 0; mt < 4; ++mt)
#pragma unroll
                for (int nt = 0; nt < 4; ++nt) {
                    mma16816(acc[mt][nt], ah[mt], bh[nt]);
                    mma16816(acc[mt][nt], al[mt], bh[nt]);
                    mma16816(acc[mt][nt], ah[mt], bl[nt]);
                }
        }
        __syncthreads();
    }

    // ---- epilogue ----
    const int r0base = m0 + wm * 64 + (lane >> 2);
    const int cbase  = n0 + wn * 32 + (lane & 3) * 2;
#pragma unroll
    for (int mt = 0; mt < 4; ++mt) {
#pragma unroll
        for (int nt = 0; nt < 4; ++nt) {
            const int cB = cbase + nt * 8;
            const float b0v = bias[cB], b1v = bias[cB + 1];
            float c0 = acc[mt][nt][0] + b0v, c1 = acc[mt][nt][1] + b1v;
            float c2 = acc[mt][nt][2] + b0v, c3 = acc[mt][nt][3] + b1v;
            if (RELU) {
                c0 = fmaxf(c0, 0.f); c1 = fmaxf(c1, 0.f);
                c2 = fmaxf(c2, 0.f); c3 = fmaxf(c3, 0.f);
            }
            const int gR0 = r0base + mt * 16, gR1 = gR0 + 8;
            if (OUTSPLIT == 0) {
                if (gR0 < M) *(float2*)(Cf + (size_t)gR0 * ldc + cB) = make_float2(c0, c1);
                if (gR1 < M) *(float2*)(Cf + (size_t)gR1 * ldc + cB) = make_float2(c2, c3);
            } else {
                uint32_t hp, lp;
                if (gR0 < M) {
                    split2(c0, c1, hp, lp);
                    *(uint32_t*)(Chi + (size_t)gR0 * ldc + cB) = hp;
                    *(uint32_t*)(Clo + (size_t)gR0 * ldc + cB) = lp;
                }
                if (gR1 < M) {
                    split2(c2, c3, hp, lp);
                    *(uint32_t*)(Chi + (size_t)gR1 * ldc + cB) = hp;
                    *(uint32_t*)(Clo + (size_t)gR1 * ldc + cB) = lp;
                }
            }
        }
    }
}

// ---------------- weight prep: transpose + hi/lo split ----------------
__global__ void split_weightT_kernel(const float* __restrict__ W, int K, int N,
                                     __nv_bfloat16* __restrict__ hi,
                                     __nv_bfloat16* __restrict__ lo)
{
    int i = blockIdx.x * blockDim.x + threadIdx.x;
    if (i >= K * N) return;
    int k = i / N, n = i % N;
    float v = W[i];
    __nv_bfloat16 h = __float2bfloat16(v);
    __nv_bfloat16 l = __float2bfloat16(v - __bfloat162float(h));
    hi[(size_t)n * K + k] = h;
    lo[(size_t)n * K + k] = l;
}

// ---------------- elementwise / glue kernels ----------------
__global__ void init_h_kernel(const int* __restrict__ nodes, const float* __restrict__ embed)
{
    int i = blockIdx.x * blockDim.x + threadIdx.x;
    if (i >= N_TOTAL * D) return;
    int row = i >> 7, c = i & 127;
    g_h[i] = embed[nodes[row / WINDOW] * D + c];
}
__global__ void edge_idx_kernel(const int* __restrict__ ie)
{
    int e = blockIdx.x * blockDim.x + threadIdx.x;
    if (e >= NE) return;
    int tt = ie[e * 3 + 0], s = ie[e * 3 + 1], d2 = ie[e * 3 + 2];
    g_nidx[e] = tt * N_NODES + s;
    g_midx[e] = tt * N_NODES + d2;
}
__global__ void zero_cnt_kernel()
{
    int i = blockIdx.x * blockDim.x + threadIdx.x;
    if (i < N_TOTAL) g_cnt[i] = 0;
}
__global__ void count_kernel()
{
    int e = blockIdx.x * blockDim.x + threadIdx.x;
    if (e < NE) atomicAdd(&g_cnt[g_midx[e]], 1);
}
__global__ void zero_agg_kernel()
{
    int i = blockIdx.x * blockDim.x + threadIdx.x;
    if (i < N_TOTAL * D) g_agg[i] = 0.f;
}
__global__ void scatter_kernel()
{
    int i = blockIdx.x * blockDim.x + threadIdx.x;
    if (i >= NE * D) return;
    int e = i >> 7, c = i & 127;
    atomicAdd(&g_agg[g_midx[e] * D + c], g_m[i]);
}
__global__ void mean_kernel()
{
    int i = blockIdx.x * blockDim.x + threadIdx.x;
    if (i >= N_TOTAL * D) return;
    int r = i >> 7;
    int c = g_cnt[r];
    g_agg[i] = (c > 0) ? g_agg[i] / (float)c : 0.f;
}
__global__ void temp_agg_kernel()
{
    int i = blockIdx.x * blockDim.x + threadIdx.x;
    if (i >= N_TOTAL * D) return;
    int v = i >> 7, c = i & 127;
    float s = 0.f; int n = 0;
    if (v >= N_NODES) { s += g_m[(v - N_NODES) * D + c]; n++; }
    if (v < TEDGE)    { s += g_m[(TEDGE + v) * D + c];   n++; }
    g_agg[i] = s / (float)n;
}
__device__ __forceinline__ float sigmoidf(float x) { return 1.f / (1.f + expf(-x)); }
__global__ void gru_kernel()
{
    int i = blockIdx.x * blockDim.x + threadIdx.x;
    if (i >= N_TOTAL * D) return;
    int r = i >> 7, c = i & 127;
    const float* xg = g_xg + (size_t)r * 384;
    const float* hg = g_hg + (size_t)r * 384;
    float z  = sigmoidf(xg[c]       + hg[c]);
    float rr = sigmoidf(xg[128 + c] + hg[128 + c]);
    float hc = tanhf(xg[256 + c] + rr * hg[256 + c]);
    float h = g_h[i];
    g_h[i] = z * h + (1.f - z) * hc;
}
__global__ void logits_softmax_kernel(const float* __restrict__ W3,
                                      const float* __restrict__ b3,
                                      float* __restrict__ out)
{
    const int row = blockIdx.x;
    const int w = threadIdx.x >> 5, lane = threadIdx.x & 31;
    __shared__ float lg[10];
    float s = 0.f;
    for (int k = lane; k < 512; k += 32)
        s += g_x2[(size_t)row * 512 + k] * W3[k * 10 + w];
#pragma unroll
    for (int o = 16; o; o >>= 1) s += __shfl_down_sync(0xffffffff, s, o);
    if (lane == 0) lg[w] = s + b3[w];
    __syncthreads();
    if (threadIdx.x == 0) {
        float mx = lg[0];
#pragma unroll
        for (int c = 1; c < 10; ++c) mx = fmaxf(mx, lg[c]);
        float e[10], sum = 0.f;
#pragma unroll
        for (int c = 0; c < 10; ++c) { e[c] = expf(lg[c] - mx); sum += e[c]; }
#pragma unroll
        for (int c = 0; c < 10; ++c) out[row * 10 + c] = e[c] / sum;
    }
}

// ---------------- host ----------------
extern "C" void kernel_launch(void* const* d_in, const int* in_sizes, int n_in,
                              void* d_out, int out_size)
{
    const int*   ie        = (const int*)  d_in[0];
    const int*   nodes     = (const int*)  d_in[1];
    const float* embed     = (const float*)d_in[2];
    const float* msg_W1    = (const float*)d_in[3];
    const float* msg_b1    = (const float*)d_in[4];
    const float* msg_W2    = (const float*)d_in[5];
    const float* msg_b2    = (const float*)d_in[6];
    const float* gru_int_W = (const float*)d_in[7];
    const float* gru_int_U = (const float*)d_in[8];
    const float* gru_int_b = (const float*)d_in[9];
    const float* gru_tmp_W = (const float*)d_in[10];
    const float* gru_tmp_U = (const float*)d_in[11];
    const float* gru_tmp_b = (const float*)d_in[12];
    const float* ro_W1     = (const float*)d_in[13];
    const float* ro_b1     = (const float*)d_in[14];
    const float* ro_W2     = (const float*)d_in[15];
    const float* ro_b2     = (const float*)d_in[16];
    const float* ro_W3     = (const float*)d_in[17];
    const float* ro_b3     = (const float*)d_in[18];
    float* out = (float*)d_out;

    float *h_p, *m_p, *agg_p, *xg_p, *hg_p, *x2_p;
    int *nidx_p, *midx_p;
    __nv_bfloat16 *hidh_p, *hidl_p;
    __nv_bfloat16 *w1h, *w1l, *w2h, *w2l, *gih, *gil, *guh, *gul, *gth, *gtl, *gvh, *gvl, *r1h, *r1l, *r2h, *r2l;
    cudaGetSymbolAddress((void**)&h_p, g_h);
    cudaGetSymbolAddress((void**)&m_p, g_m);
    cudaGetSymbolAddress((void**)&agg_p, g_agg);
    cudaGetSymbolAddress((void**)&xg_p, g_xg);
    cudaGetSymbolAddress((void**)&hg_p, g_hg);
    cudaGetSymbolAddress((void**)&x2_p, g_x2);
    cudaGetSymbolAddress((void**)&nidx_p, g_nidx);
    cudaGetSymbolAddress((void**)&midx_p, g_midx);
    cudaGetSymbolAddress((void**)&hidh_p, g_hid_hi);
    cudaGetSymbolAddress((void**)&hidl_p, g_hid_lo);
    cudaGetSymbolAddress((void**)&w1h, g_W1t_hi); cudaGetSymbolAddress((void**)&w1l, g_W1t_lo);
    cudaGetSymbolAddress((void**)&w2h, g_W2t_hi); cudaGetSymbolAddress((void**)&w2l, g_W2t_lo);
    cudaGetSymbolAddress((void**)&gih, g_GiW_hi); cudaGetSymbolAddress((void**)&gil, g_GiW_lo);
    cudaGetSymbolAddress((void**)&guh, g_GiU_hi); cudaGetSymbolAddress((void**)&gul, g_GiU_lo);
    cudaGetSymbolAddress((void**)&gth, g_GtW_hi); cudaGetSymbolAddress((void**)&gtl, g_GtW_lo);
    cudaGetSymbolAddress((void**)&gvh, g_GtU_hi); cudaGetSymbolAddress((void**)&gvl, g_GtU_lo);
    cudaGetSymbolAddress((void**)&r1h, g_R1t_hi); cudaGetSymbolAddress((void**)&r1l, g_R1t_lo);
    cudaGetSymbolAddress((void**)&r2h, g_R2t_hi); cudaGetSymbolAddress((void**)&r2l, g_R2t_lo);

    cudaFuncSetAttribute(hmma_gemm<1,1,1>, cudaFuncAttributeMaxDynamicSharedMemorySize, SMEM_BYTES);
    cudaFuncSetAttribute(hmma_gemm<2,1,1>, cudaFuncAttributeMaxDynamicSharedMemorySize, SMEM_BYTES);
    cudaFuncSetAttribute(hmma_gemm<3,0,1>, cudaFuncAttributeMaxDynamicSharedMemorySize, SMEM_BYTES);
    cudaFuncSetAttribute(hmma_gemm<0,0,0>, cudaFuncAttributeMaxDynamicSharedMemorySize, SMEM_BYTES);
    cudaFuncSetAttribute(hmma_gemm<0,1,1>, cudaFuncAttributeMaxDynamicSharedMemorySize, SMEM_BYTES);

    const int EL = 256;
    split_weightT_kernel<<<(256*HID + EL-1)/EL, EL>>>(msg_W1, 256, HID, w1h, w1l);
    split_weightT_kernel<<<(HID*D   + EL-1)/EL, EL>>>(msg_W2, HID, D,   w2h, w2l);
    split_weightT_kernel<<<(D*384   + EL-1)/EL, EL>>>(gru_int_W, D, 384, gih, gil);
    split_weightT_kernel<<<(D*384   + EL-1)/EL, EL>>>(gru_int_U, D, 384, guh, gul);
    split_weightT_kernel<<<(D*384   + EL-1)/EL, EL>>>(gru_tmp_W, D, 384, gth, gtl);
    split_weightT_kernel<<<(D*384   + EL-1)/EL, EL>>>(gru_tmp_U, D, 384, gvh, gvl);
    split_weightT_kernel<<<(D*HID   + EL-1)/EL, EL>>>(ro_W1, D, HID, r1h, r1l);
    split_weightT_kernel<<<(HID*512 + EL-1)/EL, EL>>>(ro_W2, HID, 512, r2h, r2l);

    init_h_kernel<<<(N_TOTAL*D + EL-1)/EL, EL>>>(nodes, embed);
    edge_idx_kernel<<<(NE + EL-1)/EL, EL>>>(ie);
    zero_cnt_kernel<<<(N_TOTAL + EL-1)/EL, EL>>>();
    count_kernel<<<(NE + EL-1)/EL, EL>>>();

    const int MT_E = NE / 128;                 // 1024
    const int MT_T = (TE2 + 127) / 128;        // 704
    const int MT_N = (N_TOTAL + 127) / 128;    // 391
    const int MT_R = (N_NODES + 127) / 128;    // 40

    for (int it = 0; it < 2; ++it) {
        // ---- interaction stage ----
        hmma_gemm<1,1,1><<<dim3(8, MT_E), 256, SMEM_BYTES>>>(
            nullptr, nullptr, nullptr, 0, nidx_p, midx_p,
            w1h, w1l, msg_b1, nullptr, hidh_p, hidl_p, HID, NE, 256);
        hmma_gemm<3,0,1><<<dim3(1, MT_E), 256, SMEM_BYTES>>>(
            nullptr, hidh_p, hidl_p, HID, nullptr, nullptr,
            w2h, w2l, msg_b2, m_p, nullptr, nullptr, D, NE, HID);
        zero_agg_kernel<<<(N_TOTAL*D + EL-1)/EL, EL>>>();
        scatter_kernel<<<(NE*D + EL-1)/EL, EL>>>();
        mean_kernel<<<(N_TOTAL*D + EL-1)/EL, EL>>>();
        hmma_gemm<0,0,0><<<dim3(3, MT_N), 256, SMEM_BYTES>>>(
            agg_p, nullptr, nullptr, D, nullptr, nullptr,
            gih, gil, gru_int_b, xg_p, nullptr, nullptr, 384, N_TOTAL, D);
        hmma_gemm<0,0,0><<<dim3(3, MT_N), 256, SMEM_BYTES>>>(
            h_p, nullptr, nullptr, D, nullptr, nullptr,
            guh, gul, gru_int_b + 384, hg_p, nullptr, nullptr, 384, N_TOTAL, D);
        gru_kernel<<<(N_TOTAL*D + EL-1)/EL, EL>>>();

        // ---- temporal stage ----
        hmma_gemm<2,1,1><<<dim3(8, MT_T), 256, SMEM_BYTES>>>(
            nullptr, nullptr, nullptr, 0, nullptr, nullptr,
            w1h, w1l, msg_b1, nullptr, hidh_p, hidl_p, HID, TE2, 256);
        hmma_gemm<3,0,1><<<dim3(1, MT_T), 256, SMEM_BYTES>>>(
            nullptr, hidh_p, hidl_p, HID, nullptr, nullptr,
            w2h, w2l, msg_b2, m_p, nullptr, nullptr, D, TE2, HID);
        temp_agg_kernel<<<(N_TOTAL*D + EL-1)/EL, EL>>>();
        hmma_gemm<0,0,0><<<dim3(3, MT_N), 256, SMEM_BYTES>>>(
            agg_p, nullptr, nullptr, D, nullptr, nullptr,
            gth, gtl, gru_tmp_b, xg_p, nullptr, nullptr, 384, N_TOTAL, D);
        hmma_gemm<0,0,0><<<dim3(3, MT_N), 256, SMEM_BYTES>>>(
            h_p, nullptr, nullptr, D, nullptr, nullptr,
            gvh, gvl, gru_tmp_b + 384, hg_p, nullptr, nullptr, 384, N_TOTAL, D);
        gru_kernel<<<(N_TOTAL*D + EL-1)/EL, EL>>>();
    }

    // ---- readout ----
    hmma_gemm<0,1,1><<<dim3(8, MT_R), 256, SMEM_BYTES>>>(
        h_p, nullptr, nullptr, D, nullptr, nullptr,
        r1h, r1l, ro_b1, nullptr, hidh_p, hidl_p, HID, N_NODES, D);
    hmma_gemm<3,0,1><<<dim3(4, MT_R), 256, SMEM_BYTES>>>(
        nullptr, hidh_p, hidl_p, HID, nullptr, nullptr,
        r2h, r2l, ro_b2, x2_p, nullptr, nullptr, 512, N_NODES, HID);
    logits_softmax_kernel<<<N_NODES, 320>>>(ro_W3, ro_b3, out);
}

// round 4
// speedup vs baseline: 2.5502x; 1.6590x over previous
#include <cuda_runtime.h>
#include <cuda_bf16.h>
#include <math.h>
#include <stdint.h>

#define D        128
#define N_NODES  5000
#define WINDOW   10
#define N_TOTAL  50000
#define NE       131072
#define HID      1024
#define TEDGE    45000
#define TE2      90000

// ---------------- device scratch (static, allocation-free) ----------------
__device__ __align__(16) float g_h[N_TOTAL * D];
__device__ __align__(16) float g_m[NE * D];
__device__ __align__(16) float g_agg[N_TOTAL * D];
__device__ __align__(16) float g_xg[N_TOTAL * 3 * D];
__device__ __align__(16) float g_hg[N_TOTAL * 3 * D];
__device__ int   g_cnt[N_TOTAL];
__device__ int   g_nidx[NE];
__device__ int   g_midx[NE];
__device__ __align__(16) float g_x2[N_NODES * 512];
__device__ __align__(16) float g_zero1024[1024];   // zero-initialized, never written

// node-level msg-MLP layer-1 partials: P = h@W1_top + b1, Q = h@W1_bot
__device__ __align__(16) float g_P[(size_t)N_TOTAL * HID];
__device__ __align__(16) float g_Q[(size_t)N_TOTAL * HID];

// readout hidden, split hi/lo bf16
__device__ __align__(16) __nv_bfloat16 g_hid_hi[(size_t)N_NODES * HID];
__device__ __align__(16) __nv_bfloat16 g_hid_lo[(size_t)N_NODES * HID];

// transposed + split weights, layout [N][K] (K contiguous)
__device__ __align__(16) __nv_bfloat16 g_W1t_hi[HID * 256], g_W1t_lo[HID * 256];
__device__ __align__(16) __nv_bfloat16 g_W2t_hi[D * HID],   g_W2t_lo[D * HID];
__device__ __align__(16) __nv_bfloat16 g_GiW_hi[384 * D],   g_GiW_lo[384 * D];
__device__ __align__(16) __nv_bfloat16 g_GiU_hi[384 * D],   g_GiU_lo[384 * D];
__device__ __align__(16) __nv_bfloat16 g_GtW_hi[384 * D],   g_GtW_lo[384 * D];
__device__ __align__(16) __nv_bfloat16 g_GtU_hi[384 * D],   g_GtU_lo[384 * D];
__device__ __align__(16) __nv_bfloat16 g_R1t_hi[HID * D],   g_R1t_lo[HID * D];
__device__ __align__(16) __nv_bfloat16 g_R2t_hi[512 * HID], g_R2t_lo[512 * HID];

// ---------------- helpers ----------------
__device__ __forceinline__ uint32_t smem_u32(const void* p) {
    uint32_t a;
    asm("{ .reg .u64 t; cvta.to.shared.u64 t, %1; cvt.u32.u64 %0, t; }" : "=r"(a) : "l"(p));
    return a;
}
__device__ __forceinline__ void ldsm4(uint32_t& r0, uint32_t& r1, uint32_t& r2, uint32_t& r3, uint32_t addr) {
    asm volatile("ldmatrix.sync.aligned.m8n8.x4.shared.b16 {%0,%1,%2,%3}, [%4];"
                 : "=r"(r0), "=r"(r1), "=r"(r2), "=r"(r3) : "r"(addr));
}
__device__ __forceinline__ void mma16816(float* c, const uint32_t* a, const uint32_t* b) {
    asm volatile("mma.sync.aligned.m16n8k16.row.col.f32.bf16.bf16.f32 "
                 "{%0,%1,%2,%3}, {%4,%5,%6,%7}, {%8,%9}, {%0,%1,%2,%3};"
                 : "+f"(c[0]), "+f"(c[1]), "+f"(c[2]), "+f"(c[3])
                 : "r"(a[0]), "r"(a[1]), "r"(a[2]), "r"(a[3]), "r"(b[0]), "r"(b[1]));
}
__device__ __forceinline__ void split2(float x, float y, uint32_t& h, uint32_t& l) {
    __nv_bfloat16 hx = __float2bfloat16(x);
    __nv_bfloat16 hy = __float2bfloat16(y);
    __nv_bfloat16 lx = __float2bfloat16(x - __bfloat162float(hx));
    __nv_bfloat16 ly = __float2bfloat16(y - __bfloat162float(hy));
    h = ((uint32_t)__bfloat16_as_ushort(hy) << 16) | (uint32_t)__bfloat16_as_ushort(hx);
    l = ((uint32_t)__bfloat16_as_ushort(ly) << 16) | (uint32_t)__bfloat16_as_ushort(lx);
}

// ---------------- HMMA split-bf16 GEMM ----------------
// C[M, Ncols] = act( A'[M,K] @ W[K,Ncols] + bias ), CTA 128x128, Kstep 32.
// B pre-split/transposed: Bhi/Blo layout [N][ldb].
// AMODE 0: A fp32 row-major stride lda (split on load)
// AMODE 3: A pre-split bf16 hi/lo, row-major stride lda
// AMODE 4: A[r,k] = relu(P[nidx[r]][k] + Q[midx[r]][k]),  K=1024 (fused msg-MLP)
// AMODE 5: same with analytic temporal src/dst indices
// OUTSPLIT 0: fp32 to Cf(ldc). OUTSPLIT 1: bf16 hi/lo to Chi/Clo(ldc).
#define ASTR   56
#define PANEL  (128 * ASTR)
#define SMEM_BYTES (4 * PANEL * 2)       // 57344

template<int AMODE, int OUTSPLIT, int RELU>
__global__ __launch_bounds__(256, 2)
void hmma_gemm(const float* __restrict__ Af,
               const float* __restrict__ Qf,
               const __nv_bfloat16* __restrict__ Ahi_g,
               const __nv_bfloat16* __restrict__ Alo_g,
               int lda,
               const int* __restrict__ idxA, const int* __restrict__ idxB,
               const __nv_bfloat16* __restrict__ Bhi, const __nv_bfloat16* __restrict__ Blo,
               int ldb,
               const float* __restrict__ bias,
               float* __restrict__ Cf,
               __nv_bfloat16* __restrict__ Chi, __nv_bfloat16* __restrict__ Clo,
               int ldc, int M, int K)
{
    extern __shared__ __nv_bfloat16 smbuf[];
    __nv_bfloat16* sAhi = smbuf;
    __nv_bfloat16* sAlo = sAhi + PANEL;
    __nv_bfloat16* sBhi = sAlo + PANEL;
    __nv_bfloat16* sBlo = sBhi + PANEL;
    const uint32_t sbase = smem_u32(smbuf);
    const uint32_t OFF_ALO = PANEL * 2;
    const uint32_t OFF_BHI = 2 * PANEL * 2;
    const uint32_t OFF_BLO = 3 * PANEL * 2;

    const int t = threadIdx.x, lane = t & 31, w = t >> 5;
    const int wm = w >> 2, wn = w & 3;
    const int m0 = blockIdx.y * 128, n0 = blockIdx.x * 128;

    float acc[4][4][4];
#pragma unroll
    for (int i = 0; i < 4; ++i)
#pragma unroll
        for (int j = 0; j < 4; ++j)
#pragma unroll
            for (int q = 0; q < 4; ++q) acc[i][j][q] = 0.f;

    const int lrow = t >> 1;
    const int lhalf = t & 1;

    const int steps = K >> 5;
    for (int s = 0; s < steps; ++s) {
        const int k0 = s << 5;
        // ---- A panel (128 x 32) hi/lo ----
        {
            int gRow = m0 + lrow; if (gRow >= M) gRow = M - 1;
            __nv_bfloat16* dh = sAhi + lrow * ASTR + lhalf * 16;
            __nv_bfloat16* dl = sAlo + lrow * ASTR + lhalf * 16;
            if (AMODE == 3) {
                const size_t off = (size_t)gRow * lda + k0 + lhalf * 16;
                *(uint4*)dh       = *(const uint4*)(Ahi_g + off);
                *(uint4*)(dh + 8) = *(const uint4*)(Ahi_g + off + 8);
                *(uint4*)dl       = *(const uint4*)(Alo_g + off);
                *(uint4*)(dl + 8) = *(const uint4*)(Alo_g + off + 8);
            } else {
                float vv[16];
                if (AMODE == 0) {
                    const float* src = Af + (size_t)gRow * lda + k0 + lhalf * 16;
#pragma unroll
                    for (int i = 0; i < 16; i += 4) {
                        float4 v = *(const float4*)(src + i);
                        vv[i] = v.x; vv[i+1] = v.y; vv[i+2] = v.z; vv[i+3] = v.w;
                    }
                } else {  // AMODE 4/5: fused relu(P + Q)
                    int n_, m_;
                    if (AMODE == 4) { n_ = idxA[gRow]; m_ = idxB[gRow]; }
                    else {
                        if (gRow < TEDGE) { n_ = gRow;                   m_ = gRow + N_NODES; }
                        else              { n_ = gRow - TEDGE + N_NODES; m_ = gRow - TEDGE;   }
                    }
                    const float* p = Af + (size_t)n_ * HID + k0 + lhalf * 16;
                    const float* q = Qf + (size_t)m_ * HID + k0 + lhalf * 16;
#pragma unroll
                    for (int i = 0; i < 16; i += 4) {
                        float4 a = *(const float4*)(p + i);
                        float4 b = *(const float4*)(q + i);
                        vv[i]   = fmaxf(a.x + b.x, 0.f);
                        vv[i+1] = fmaxf(a.y + b.y, 0.f);
                        vv[i+2] = fmaxf(a.z + b.z, 0.f);
                        vv[i+3] = fmaxf(a.w + b.w, 0.f);
                    }
                }
                uint32_t h[8], l[8];
#pragma unroll
                for (int i = 0; i < 8; ++i) split2(vv[2*i], vv[2*i+1], h[i], l[i]);
                *(uint4*)dh       = make_uint4(h[0], h[1], h[2], h[3]);
                *(uint4*)(dh + 8) = make_uint4(h[4], h[5], h[6], h[7]);
                *(uint4*)dl       = make_uint4(l[0], l[1], l[2], l[3]);
                *(uint4*)(dl + 8) = make_uint4(l[4], l[5], l[6], l[7]);
            }
        }
        // ---- B panel (128 n-rows x 32 k) hi/lo ----
        {
            const size_t off = (size_t)(n0 + lrow) * ldb + k0 + lhalf * 16;
            __nv_bfloat16* dh = sBhi + lrow * ASTR + lhalf * 16;
            __nv_bfloat16* dl = sBlo + lrow * ASTR + lhalf * 16;
            *(uint4*)dh       = *(const uint4*)(Bhi + off);
            *(uint4*)(dh + 8) = *(const uint4*)(Bhi + off + 8);
            *(uint4*)dl       = *(const uint4*)(Blo + off);
            *(uint4*)(dl + 8) = *(const uint4*)(Blo + off + 8);
        }
        __syncthreads();

#pragma unroll
        for (int kk = 0; kk < 2; ++kk) {
            const int kc = kk * 16;
            uint32_t ah[4][4], al[4][4];
#pragma unroll
            for (int mt = 0; mt < 4; ++mt) {
                const uint32_t aoff =
                    ((uint32_t)((wm * 64 + mt * 16 + (lane & 15)) * ASTR + kc + ((lane >> 4) << 3))) << 1;
                ldsm4(ah[mt][0], ah[mt][1], ah[mt][2], ah[mt][3], sbase + aoff);
                ldsm4(al[mt][0], al[mt][1], al[mt][2], al[mt][3], sbase + OFF_ALO + aoff);
            }
            uint32_t bh[4][2], bl[4][2];
#pragma unroll
            for (int p = 0; p < 2; ++p) {
                const uint32_t boff =
                    ((uint32_t)((wn * 32 + p * 16 + ((lane >> 4) << 3) + (lane & 7)) * ASTR
                                + kc + (((lane >> 3) & 1) << 3))) << 1;
                uint32_t r0, r1, r2, r3;
                ldsm4(r0, r1, r2, r3, sbase + OFF_BHI + boff);
                bh[p * 2][0] = r0; bh[p * 2][1] = r1; bh[p * 2 + 1][0] = r2; bh[p * 2 + 1][1] = r3;
                ldsm4(r0, r1, r2, r3, sbase + OFF_BLO + boff);
                bl[p * 2][0] = r0; bl[p * 2][1] = r1; bl[p * 2 + 1][0] = r2; bl[p * 2 + 1][1] = r3;
            }
#pragma unroll
            for (int mt = 0; mt < 4; ++mt)
#pragma unroll
                for (int nt = 0; nt < 4; ++nt) {
                    mma16816(acc[mt][nt], ah[mt], bh[nt]);
                    mma16816(acc[mt][nt], al[mt], bh[nt]);
                    mma16816(acc[mt][nt], ah[mt], bl[nt]);
                }
        }
        __syncthreads();
    }

    // ---- epilogue ----
    const int r0base = m0 + wm * 64 + (lane >> 2);
    const int cbase  = n0 + wn * 32 + (lane & 3) * 2;
#pragma unroll
    for (int mt = 0; mt < 4; ++mt) {
#pragma unroll
        for (int nt = 0; nt < 4; ++nt) {
            const int cB = cbase + nt * 8;
            const float b0v = bias[cB], b1v = bias[cB + 1];
            float c0 = acc[mt][nt][0] + b0v, c1 = acc[mt][nt][1] + b1v;
            float c2 = acc[mt][nt][2] + b0v, c3 = acc[mt][nt][3] + b1v;
            if (RELU) {
                c0 = fmaxf(c0, 0.f); c1 = fmaxf(c1, 0.f);
                c2 = fmaxf(c2, 0.f); c3 = fmaxf(c3, 0.f);
            }
            const int gR0 = r0base + mt * 16, gR1 = gR0 + 8;
            if (OUTSPLIT == 0) {
                if (gR0 < M) *(float2*)(Cf + (size_t)gR0 * ldc + cB) = make_float2(c0, c1);
                if (gR1 < M) *(float2*)(Cf + (size_t)gR1 * ldc + cB) = make_float2(c2, c3);
            } else {
                uint32_t hp, lp;
                if (gR0 < M) {
                    split2(c0, c1, hp, lp);
                    *(uint32_t*)(Chi + (size_t)gR0 * ldc + cB) = hp;
                    *(uint32_t*)(Clo + (size_t)gR0 * ldc + cB) = lp;
                }
                if (gR1 < M) {
                    split2(c2, c3, hp, lp);
                    *(uint32_t*)(Chi + (size_t)gR1 * ldc + cB) = hp;
                    *(uint32_t*)(Clo + (size_t)gR1 * ldc + cB) = lp;
                }
            }
        }
    }
}

// ---------------- weight prep: transpose + hi/lo split ----------------
__global__ void split_weightT_kernel(const float* __restrict__ W, int K, int N,
                                     __nv_bfloat16* __restrict__ hi,
                                     __nv_bfloat16* __restrict__ lo)
{
    int i = blockIdx.x * blockDim.x + threadIdx.x;
    if (i >= K * N) return;
    int k = i / N, n = i % N;
    float v = W[i];
    __nv_bfloat16 h = __float2bfloat16(v);
    __nv_bfloat16 l = __float2bfloat16(v - __bfloat162float(h));
    hi[(size_t)n * K + k] = h;
    lo[(size_t)n * K + k] = l;
}

// ---------------- elementwise / glue kernels ----------------
__global__ void init_h_kernel(const int* __restrict__ nodes, const float* __restrict__ embed)
{
    int i = blockIdx.x * blockDim.x + threadIdx.x;
    if (i >= N_TOTAL * D) return;
    int row = i >> 7, c = i & 127;
    g_h[i] = embed[nodes[row / WINDOW] * D + c];
}
__global__ void edge_idx_kernel(const int* __restrict__ ie)
{
    int e = blockIdx.x * blockDim.x + threadIdx.x;
    if (e >= NE) return;
    int tt = ie[e * 3 + 0], s = ie[e * 3 + 1], d2 = ie[e * 3 + 2];
    g_nidx[e] = tt * N_NODES + s;
    g_midx[e] = tt * N_NODES + d2;
}
__global__ void zero_cnt_kernel()
{
    int i = blockIdx.x * blockDim.x + threadIdx.x;
    if (i < N_TOTAL) g_cnt[i] = 0;
}
__global__ void count_kernel()
{
    int e = blockIdx.x * blockDim.x + threadIdx.x;
    if (e < NE) atomicAdd(&g_cnt[g_midx[e]], 1);
}
__global__ void zero_agg_kernel()
{
    int i = blockIdx.x * blockDim.x + threadIdx.x;
    if (i < N_TOTAL * D) g_agg[i] = 0.f;
}
__global__ void scatter_kernel()
{
    int i = blockIdx.x * blockDim.x + threadIdx.x;
    if (i >= NE * D) return;
    int e = i >> 7, c = i & 127;
    atomicAdd(&g_agg[g_midx[e] * D + c], g_m[i]);
}
__global__ void mean_kernel()
{
    int i = blockIdx.x * blockDim.x + threadIdx.x;
    if (i >= N_TOTAL * D) return;
    int r = i >> 7;
    int c = g_cnt[r];
    g_agg[i] = (c > 0) ? g_agg[i] / (float)c : 0.f;
}
__global__ void temp_agg_kernel()
{
    int i = blockIdx.x * blockDim.x + threadIdx.x;
    if (i >= N_TOTAL * D) return;
    int v = i >> 7, c = i & 127;
    float s = 0.f; int n = 0;
    if (v >= N_NODES) { s += g_m[(v - N_NODES) * D + c]; n++; }
    if (v < TEDGE)    { s += g_m[(TEDGE + v) * D + c];   n++; }
    g_agg[i] = s / (float)n;
}
__device__ __forceinline__ float sigmoidf(float x) { return 1.f / (1.f + expf(-x)); }
__global__ void gru_kernel()
{
    int i = blockIdx.x * blockDim.x + threadIdx.x;
    if (i >= N_TOTAL * D) return;
    int r = i >> 7, c = i & 127;
    const float* xg = g_xg + (size_t)r * 384;
    const float* hg = g_hg + (size_t)r * 384;
    float z  = sigmoidf(xg[c]       + hg[c]);
    float rr = sigmoidf(xg[128 + c] + hg[128 + c]);
    float hc = tanhf(xg[256 + c] + rr * hg[256 + c]);
    float h = g_h[i];
    g_h[i] = z * h + (1.f - z) * hc;
}
__global__ void logits_softmax_kernel(const float* __restrict__ W3,
                                      const float* __restrict__ b3,
                                      float* __restrict__ out)
{
    const int row = blockIdx.x;
    const int w = threadIdx.x >> 5, lane = threadIdx.x & 31;
    __shared__ float lg[10];
    float s = 0.f;
    for (int k = lane; k < 512; k += 32)
        s += g_x2[(size_t)row * 512 + k] * W3[k * 10 + w];
#pragma unroll
    for (int o = 16; o; o >>= 1) s += __shfl_down_sync(0xffffffff, s, o);
    if (lane == 0) lg[w] = s + b3[w];
    __syncthreads();
    if (threadIdx.x == 0) {
        float mx = lg[0];
#pragma unroll
        for (int c = 1; c < 10; ++c) mx = fmaxf(mx, lg[c]);
        float e[10], sum = 0.f;
#pragma unroll
        for (int c = 0; c < 10; ++c) { e[c] = expf(lg[c] - mx); sum += e[c]; }
#pragma unroll
        for (int c = 0; c < 10; ++c) out[row * 10 + c] = e[c] / sum;
    }
}

// ---------------- host ----------------
extern "C" void kernel_launch(void* const* d_in, const int* in_sizes, int n_in,
                              void* d_out, int out_size)
{
    const int*   ie        = (const int*)  d_in[0];
    const int*   nodes     = (const int*)  d_in[1];
    const float* embed     = (const float*)d_in[2];
    const float* msg_W1    = (const float*)d_in[3];
    const float* msg_b1    = (const float*)d_in[4];
    const float* msg_W2    = (const float*)d_in[5];
    const float* msg_b2    = (const float*)d_in[6];
    const float* gru_int_W = (const float*)d_in[7];
    const float* gru_int_U = (const float*)d_in[8];
    const float* gru_int_b = (const float*)d_in[9];
    const float* gru_tmp_W = (const float*)d_in[10];
    const float* gru_tmp_U = (const float*)d_in[11];
    const float* gru_tmp_b = (const float*)d_in[12];
    const float* ro_W1     = (const float*)d_in[13];
    const float* ro_b1     = (const float*)d_in[14];
    const float* ro_W2     = (const float*)d_in[15];
    const float* ro_b2     = (const float*)d_in[16];
    const float* ro_W3     = (const float*)d_in[17];
    const float* ro_b3     = (const float*)d_in[18];
    float* out = (float*)d_out;

    float *h_p, *m_p, *agg_p, *xg_p, *hg_p, *x2_p, *P_p, *Q_p, *zero_p;
    int *nidx_p, *midx_p;
    __nv_bfloat16 *hidh_p, *hidl_p;
    __nv_bfloat16 *w1h, *w1l, *w2h, *w2l, *gih, *gil, *guh, *gul, *gth, *gtl, *gvh, *gvl, *r1h, *r1l, *r2h, *r2l;
    cudaGetSymbolAddress((void**)&h_p, g_h);
    cudaGetSymbolAddress((void**)&m_p, g_m);
    cudaGetSymbolAddress((void**)&agg_p, g_agg);
    cudaGetSymbolAddress((void**)&xg_p, g_xg);
    cudaGetSymbolAddress((void**)&hg_p, g_hg);
    cudaGetSymbolAddress((void**)&x2_p, g_x2);
    cudaGetSymbolAddress((void**)&P_p, g_P);
    cudaGetSymbolAddress((void**)&Q_p, g_Q);
    cudaGetSymbolAddress((void**)&zero_p, g_zero1024);
    cudaGetSymbolAddress((void**)&nidx_p, g_nidx);
    cudaGetSymbolAddress((void**)&midx_p, g_midx);
    cudaGetSymbolAddress((void**)&hidh_p, g_hid_hi);
    cudaGetSymbolAddress((void**)&hidl_p, g_hid_lo);
    cudaGetSymbolAddress((void**)&w1h, g_W1t_hi); cudaGetSymbolAddress((void**)&w1l, g_W1t_lo);
    cudaGetSymbolAddress((void**)&w2h, g_W2t_hi); cudaGetSymbolAddress((void**)&w2l, g_W2t_lo);
    cudaGetSymbolAddress((void**)&gih, g_GiW_hi); cudaGetSymbolAddress((void**)&gil, g_GiW_lo);
    cudaGetSymbolAddress((void**)&guh, g_GiU_hi); cudaGetSymbolAddress((void**)&gul, g_GiU_lo);
    cudaGetSymbolAddress((void**)&gth, g_GtW_hi); cudaGetSymbolAddress((void**)&gtl, g_GtW_lo);
    cudaGetSymbolAddress((void**)&gvh, g_GtU_hi); cudaGetSymbolAddress((void**)&gvl, g_GtU_lo);
    cudaGetSymbolAddress((void**)&r1h, g_R1t_hi); cudaGetSymbolAddress((void**)&r1l, g_R1t_lo);
    cudaGetSymbolAddress((void**)&r2h, g_R2t_hi); cudaGetSymbolAddress((void**)&r2l, g_R2t_lo);

    cudaFuncSetAttribute(hmma_gemm<0,0,0>, cudaFuncAttributeMaxDynamicSharedMemorySize, SMEM_BYTES);
    cudaFuncSetAttribute(hmma_gemm<0,1,1>, cudaFuncAttributeMaxDynamicSharedMemorySize, SMEM_BYTES);
    cudaFuncSetAttribute(hmma_gemm<3,0,1>, cudaFuncAttributeMaxDynamicSharedMemorySize, SMEM_BYTES);
    cudaFuncSetAttribute(hmma_gemm<4,0,1>, cudaFuncAttributeMaxDynamicSharedMemorySize, SMEM_BYTES);
    cudaFuncSetAttribute(hmma_gemm<5,0,1>, cudaFuncAttributeMaxDynamicSharedMemorySize, SMEM_BYTES);

    const int EL = 256;
    split_weightT_kernel<<<(256*HID + EL-1)/EL, EL>>>(msg_W1, 256, HID, w1h, w1l);
    split_weightT_kernel<<<(HID*D   + EL-1)/EL, EL>>>(msg_W2, HID, D,   w2h, w2l);
    split_weightT_kernel<<<(D*384   + EL-1)/EL, EL>>>(gru_int_W, D, 384, gih, gil);
    split_weightT_kernel<<<(D*384   + EL-1)/EL, EL>>>(gru_int_U, D, 384, guh, gul);
    split_weightT_kernel<<<(D*384   + EL-1)/EL, EL>>>(gru_tmp_W, D, 384, gth, gtl);
    split_weightT_kernel<<<(D*384   + EL-1)/EL, EL>>>(gru_tmp_U, D, 384, gvh, gvl);
    split_weightT_kernel<<<(D*HID   + EL-1)/EL, EL>>>(ro_W1, D, HID, r1h, r1l);
    split_weightT_kernel<<<(HID*512 + EL-1)/EL, EL>>>(ro_W2, HID, 512, r2h, r2l);

    init_h_kernel<<<(N_TOTAL*D + EL-1)/EL, EL>>>(nodes, embed);
    edge_idx_kernel<<<(NE + EL-1)/EL, EL>>>(ie);
    zero_cnt_kernel<<<(N_TOTAL + EL-1)/EL, EL>>>();
    count_kernel<<<(NE + EL-1)/EL, EL>>>();

    const int MT_E = NE / 128;                 // 1024
    const int MT_T = (TE2 + 127) / 128;        // 704
    const int MT_N = (N_TOTAL + 127) / 128;    // 391
    const int MT_R = (N_NODES + 127) / 128;    // 40

    for (int it = 0; it < 2; ++it) {
        // ---- interaction stage ----
        // P = h @ W1_top + b1 ; Q = h @ W1_bot
        hmma_gemm<0,0,0><<<dim3(8, MT_N), 256, SMEM_BYTES>>>(
            h_p, nullptr, nullptr, nullptr, D, nullptr, nullptr,
            w1h, w1l, 256, msg_b1, P_p, nullptr, nullptr, HID, N_TOTAL, D);
        hmma_gemm<0,0,0><<<dim3(8, MT_N), 256, SMEM_BYTES>>>(
            h_p, nullptr, nullptr, nullptr, D, nullptr, nullptr,
            w1h + 128, w1l + 128, 256, zero_p, Q_p, nullptr, nullptr, HID, N_TOTAL, D);
        // m = relu( relu(P[n]+Q[m]) @ W2 + b2 ) fused
        hmma_gemm<4,0,1><<<dim3(1, MT_E), 256, SMEM_BYTES>>>(
            P_p, Q_p, nullptr, nullptr, 0, nidx_p, midx_p,
            w2h, w2l, HID, msg_b2, m_p, nullptr, nullptr, D, NE, HID);
        zero_agg_kernel<<<(N_TOTAL*D + EL-1)/EL, EL>>>();
        scatter_kernel<<<(NE*D + EL-1)/EL, EL>>>();
        mean_kernel<<<(N_TOTAL*D + EL-1)/EL, EL>>>();
        hmma_gemm<0,0,0><<<dim3(3, MT_N), 256, SMEM_BYTES>>>(
            agg_p, nullptr, nullptr, nullptr, D, nullptr, nullptr,
            gih, gil, D, gru_int_b, xg_p, nullptr, nullptr, 384, N_TOTAL, D);
        hmma_gemm<0,0,0><<<dim3(3, MT_N), 256, SMEM_BYTES>>>(
            h_p, nullptr, nullptr, nullptr, D, nullptr, nullptr,
            guh, gul, D, gru_int_b + 384, hg_p, nullptr, nullptr, 384, N_TOTAL, D);
        gru_kernel<<<(N_TOTAL*D + EL-1)/EL, EL>>>();

        // ---- temporal stage ----
        hmma_gemm<0,0,0><<<dim3(8, MT_N), 256, SMEM_BYTES>>>(
            h_p, nullptr, nullptr, nullptr, D, nullptr, nullptr,
            w1h, w1l, 256, msg_b1, P_p, nullptr, nullptr, HID, N_TOTAL, D);
        hmma_gemm<0,0,0><<<dim3(8, MT_N), 256, SMEM_BYTES>>>(
            h_p, nullptr, nullptr, nullptr, D, nullptr, nullptr,
            w1h + 128, w1l + 128, 256, zero_p, Q_p, nullptr, nullptr, HID, N_TOTAL, D);
        hmma_gemm<5,0,1><<<dim3(1, MT_T), 256, SMEM_BYTES>>>(
            P_p, Q_p, nullptr, nullptr, 0, nullptr, nullptr,
            w2h, w2l, HID, msg_b2, m_p, nullptr, nullptr, D, TE2, HID);
        temp_agg_kernel<<<(N_TOTAL*D + EL-1)/EL, EL>>>();
        hmma_gemm<0,0,0><<<dim3(3, MT_N), 256, SMEM_BYTES>>>(
            agg_p, nullptr, nullptr, nullptr, D, nullptr, nullptr,
            gth, gtl, D, gru_tmp_b, xg_p, nullptr, nullptr, 384, N_TOTAL, D);
        hmma_gemm<0,0,0><<<dim3(3, MT_N), 256, SMEM_BYTES>>>(
            h_p, nullptr, nullptr, nullptr, D, nullptr, nullptr,
            gvh, gvl, D, gru_tmp_b + 384, hg_p, nullptr, nullptr, 384, N_TOTAL, D);
        gru_kernel<<<(N_TOTAL*D + EL-1)/EL, EL>>>();
    }

    // ---- readout ----
    hmma_gemm<0,1,1><<<dim3(8, MT_R), 256, SMEM_BYTES>>>(
        h_p, nullptr, nullptr, nullptr, D, nullptr, nullptr,
        r1h, r1l, D, ro_b1, nullptr, hidh_p, hidl_p, HID, N_NODES, D);
    hmma_gemm<3,0,1><<<dim3(4, MT_R), 256, SMEM_BYTES>>>(
        nullptr, nullptr, hidh_p, hidl_p, HID, nullptr, nullptr,
        r2h, r2l, HID, ro_b2, x2_p, nullptr, nullptr, 512, N_NODES, HID);
    logits_softmax_kernel<<<N_NODES, 320>>>(ro_W3, ro_b3, out);
}

// round 5
// speedup vs baseline: 2.5675x; 1.0068x over previous
#include <cuda_runtime.h>
#include <cuda_bf16.h>
#include <math.h>
#include <stdint.h>

#define D        128
#define N_NODES  5000
#define WINDOW   10
#define N_TOTAL  50000
#define NE       131072
#define HID      1024
#define TEDGE    45000
#define TE2      90000

// ---------------- device scratch (static, allocation-free) ----------------
__device__ __align__(16) float g_h[N_TOTAL * D];
__device__ __align__(16) float g_m[NE * D];
__device__ __align__(16) float g_agg[N_TOTAL * D];
__device__ __align__(16) float g_xg[N_TOTAL * 3 * D];
__device__ __align__(16) float g_hg[N_TOTAL * 3 * D];
__device__ int   g_cnt[N_TOTAL];
__device__ int   g_nidx[NE];
__device__ int   g_midx[NE];
__device__ __align__(16) float g_x2[N_NODES * 512];
__device__ __align__(16) float g_zero1024[1024];

// node-level msg-MLP layer-1 partials: P = h@W1_top + b1, Q = h@W1_bot
__device__ __align__(16) float g_P[(size_t)N_TOTAL * HID];
__device__ __align__(16) float g_Q[(size_t)N_TOTAL * HID];

// readout hidden, split hi/lo bf16
__device__ __align__(16) __nv_bfloat16 g_hid_hi[(size_t)N_NODES * HID];
__device__ __align__(16) __nv_bfloat16 g_hid_lo[(size_t)N_NODES * HID];

// transposed + split weights, layout [N][K]
__device__ __align__(16) __nv_bfloat16 g_W1t_hi[HID * 256], g_W1t_lo[HID * 256];
__device__ __align__(16) __nv_bfloat16 g_W2t_hi[D * HID],   g_W2t_lo[D * HID];
__device__ __align__(16) __nv_bfloat16 g_GiW_hi[384 * D],   g_GiW_lo[384 * D];
__device__ __align__(16) __nv_bfloat16 g_GiU_hi[384 * D],   g_GiU_lo[384 * D];
__device__ __align__(16) __nv_bfloat16 g_GtW_hi[384 * D],   g_GtW_lo[384 * D];
__device__ __align__(16) __nv_bfloat16 g_GtU_hi[384 * D],   g_GtU_lo[384 * D];
__device__ __align__(16) __nv_bfloat16 g_R1t_hi[HID * D],   g_R1t_lo[HID * D];
__device__ __align__(16) __nv_bfloat16 g_R2t_hi[512 * HID], g_R2t_lo[512 * HID];

// ---------------- helpers ----------------
__device__ __forceinline__ uint32_t smem_u32(const void* p) {
    uint32_t a;
    asm("{ .reg .u64 t; cvta.to.shared.u64 t, %1; cvt.u32.u64 %0, t; }" : "=r"(a) : "l"(p));
    return a;
}
__device__ __forceinline__ void ldsm4(uint32_t& r0, uint32_t& r1, uint32_t& r2, uint32_t& r3, uint32_t addr) {
    asm volatile("ldmatrix.sync.aligned.m8n8.x4.shared.b16 {%0,%1,%2,%3}, [%4];"
                 : "=r"(r0), "=r"(r1), "=r"(r2), "=r"(r3) : "r"(addr));
}
__device__ __forceinline__ void mma16816(float* c, const uint32_t* a, const uint32_t* b) {
    asm volatile("mma.sync.aligned.m16n8k16.row.col.f32.bf16.bf16.f32 "
                 "{%0,%1,%2,%3}, {%4,%5,%6,%7}, {%8,%9}, {%0,%1,%2,%3};"
                 : "+f"(c[0]), "+f"(c[1]), "+f"(c[2]), "+f"(c[3])
                 : "r"(a[0]), "r"(a[1]), "r"(a[2]), "r"(a[3]), "r"(b[0]), "r"(b[1]));
}
__device__ __forceinline__ void cp16(uint32_t saddr, const void* g) {
    asm volatile("cp.async.cg.shared.global [%0], [%1], 16;" :: "r"(saddr), "l"(g));
}
#define CP_COMMIT() asm volatile("cp.async.commit_group;" ::: "memory")
#define CP_WAIT0()  asm volatile("cp.async.wait_group 0;" ::: "memory")

__device__ __forceinline__ void split2(float x, float y, uint32_t& h, uint32_t& l) {
    __nv_bfloat16 hx = __float2bfloat16(x);
    __nv_bfloat16 hy = __float2bfloat16(y);
    __nv_bfloat16 lx = __float2bfloat16(x - __bfloat162float(hx));
    __nv_bfloat16 ly = __float2bfloat16(y - __bfloat162float(hy));
    h = ((uint32_t)__bfloat16_as_ushort(hy) << 16) | (uint32_t)__bfloat16_as_ushort(hx);
    l = ((uint32_t)__bfloat16_as_ushort(ly) << 16) | (uint32_t)__bfloat16_as_ushort(lx);
}

// ---------------- HMMA split-bf16 GEMM, double-buffered pipeline ----------------
// AMODE 0: A fp32 row-major stride lda (split on load, register-staged)
// AMODE 3: A pre-split bf16 hi/lo (pure cp.async)
// AMODE 4: A[r,k] = relu(P[nidx[r]][k] + Q[midx[r]][k])
// AMODE 5: same with analytic temporal indices
#define ASTR   56
#define PANEL  (128 * ASTR)
#define PANELB (PANEL * 2)               // bytes per panel: 14336
#define BUF_BYTES (4 * PANELB)           // 57344
#define SMEM_BYTES (2 * BUF_BYTES)       // 114688

template<int AMODE, int OUTSPLIT, int RELU>
__global__ __launch_bounds__(256, 2)
void hmma_gemm(const float* __restrict__ Af,
               const float* __restrict__ Qf,
               const __nv_bfloat16* __restrict__ Ahi_g,
               const __nv_bfloat16* __restrict__ Alo_g,
               int lda,
               const int* __restrict__ idxA, const int* __restrict__ idxB,
               const __nv_bfloat16* __restrict__ Bhi, const __nv_bfloat16* __restrict__ Blo,
               int ldb,
               const float* __restrict__ bias,
               float* __restrict__ Cf,
               __nv_bfloat16* __restrict__ Chi, __nv_bfloat16* __restrict__ Clo,
               int ldc, int M, int K)
{
    extern __shared__ __nv_bfloat16 smbuf[];
    const uint32_t sbase = smem_u32(smbuf);

    const int t = threadIdx.x, lane = t & 31, w = t >> 5;
    const int wm = w >> 2, wn = w & 3;
    const int m0 = blockIdx.y * 128, n0 = blockIdx.x * 128;
    const int lrow = t >> 1, lhalf = t & 1;
    const uint32_t arow_off = ((uint32_t)(lrow * ASTR + lhalf * 16)) << 1;

    float acc[4][4][4];
#pragma unroll
    for (int i = 0; i < 4; ++i)
#pragma unroll
        for (int j = 0; j < 4; ++j)
#pragma unroll
            for (int q = 0; q < 4; ++q) acc[i][j][q] = 0.f;

    uint32_t rh[8], rl[8];   // A staging (non-AMODE3)

    // ---- register-staged A load ----
    auto loadA = [&](int s) {
        if (AMODE == 3) return;
        const int k0 = s << 5;
        int gRow = m0 + lrow; if (gRow >= M) gRow = M - 1;
        float vv[16];
        if (AMODE == 0) {
            const float* src = Af + (size_t)gRow * lda + k0 + lhalf * 16;
#pragma unroll
            for (int i = 0; i < 16; i += 4) {
                float4 v = *(const float4*)(src + i);
                vv[i] = v.x; vv[i+1] = v.y; vv[i+2] = v.z; vv[i+3] = v.w;
            }
        } else {
            int n_, m_;
            if (AMODE == 4) { n_ = idxA[gRow]; m_ = idxB[gRow]; }
            else {
                if (gRow < TEDGE) { n_ = gRow;                   m_ = gRow + N_NODES; }
                else              { n_ = gRow - TEDGE + N_NODES; m_ = gRow - TEDGE;   }
            }
            const float* p = Af + (size_t)n_ * HID + k0 + lhalf * 16;
            const float* q = Qf + (size_t)m_ * HID + k0 + lhalf * 16;
#pragma unroll
            for (int i = 0; i < 16; i += 4) {
                float4 a = *(const float4*)(p + i);
                float4 b = *(const float4*)(q + i);
                vv[i]   = fmaxf(a.x + b.x, 0.f);
                vv[i+1] = fmaxf(a.y + b.y, 0.f);
                vv[i+2] = fmaxf(a.z + b.z, 0.f);
                vv[i+3] = fmaxf(a.w + b.w, 0.f);
            }
        }
#pragma unroll
        for (int i = 0; i < 8; ++i) split2(vv[2*i], vv[2*i+1], rh[i], rl[i]);
    };
    auto stsA = [&](int buf) {
        if (AMODE == 3) return;
        __nv_bfloat16* base = smbuf + (size_t)buf * (BUF_BYTES / 2);
        __nv_bfloat16* dh = base + lrow * ASTR + lhalf * 16;
        __nv_bfloat16* dl = dh + PANEL;
        *(uint4*)dh       = make_uint4(rh[0], rh[1], rh[2], rh[3]);
        *(uint4*)(dh + 8) = make_uint4(rh[4], rh[5], rh[6], rh[7]);
        *(uint4*)dl       = make_uint4(rl[0], rl[1], rl[2], rl[3]);
        *(uint4*)(dl + 8) = make_uint4(rl[4], rl[5], rl[6], rl[7]);
    };
    // ---- cp.async copies ----
    auto cpaA = [&](int s, int buf) {   // AMODE 3 only
        const int k0 = s << 5;
        int gRow = m0 + lrow; if (gRow >= M) gRow = M - 1;
        const size_t off = (size_t)gRow * lda + k0 + lhalf * 16;
        const uint32_t d = sbase + buf * BUF_BYTES + arow_off;
        cp16(d,      Ahi_g + off);
        cp16(d + 16, Ahi_g + off + 8);
        cp16(d + PANELB,      Alo_g + off);
        cp16(d + PANELB + 16, Alo_g + off + 8);
    };
    auto cpaB = [&](int s, int buf) {
        const int k0 = s << 5;
        const size_t off = (size_t)(n0 + lrow) * ldb + k0 + lhalf * 16;
        const uint32_t d = sbase + buf * BUF_BYTES + 2 * PANELB + arow_off;
        cp16(d,      Bhi + off);
        cp16(d + 16, Bhi + off + 8);
        cp16(d + PANELB,      Blo + off);
        cp16(d + PANELB + 16, Blo + off + 8);
    };
    // ---- MMA phase ----
    auto domma = [&](int buf) {
        const uint32_t bb = sbase + buf * BUF_BYTES;
#pragma unroll
        for (int kk = 0; kk < 2; ++kk) {
            const int kc = kk * 16;
            uint32_t bh[4][2], bl[4][2];
#pragma unroll
            for (int p = 0; p < 2; ++p) {
                const uint32_t boff =
                    ((uint32_t)((wn * 32 + p * 16 + ((lane >> 4) << 3) + (lane & 7)) * ASTR
                                + kc + (((lane >> 3) & 1) << 3))) << 1;
                uint32_t r0, r1, r2, r3;
                ldsm4(r0, r1, r2, r3, bb + 2 * PANELB + boff);
                bh[p * 2][0] = r0; bh[p * 2][1] = r1; bh[p * 2 + 1][0] = r2; bh[p * 2 + 1][1] = r3;
                ldsm4(r0, r1, r2, r3, bb + 3 * PANELB + boff);
                bl[p * 2][0] = r0; bl[p * 2][1] = r1; bl[p * 2 + 1][0] = r2; bl[p * 2 + 1][1] = r3;
            }
#pragma unroll
            for (int mt = 0; mt < 4; ++mt) {
                const uint32_t aoff =
                    ((uint32_t)((wm * 64 + mt * 16 + (lane & 15)) * ASTR + kc + ((lane >> 4) << 3))) << 1;
                uint32_t ah[4], al[4];
                ldsm4(ah[0], ah[1], ah[2], ah[3], bb + aoff);
                ldsm4(al[0], al[1], al[2], al[3], bb + PANELB + aoff);
#pragma unroll
                for (int nt = 0; nt < 4; ++nt) {
                    mma16816(acc[mt][nt], ah, bh[nt]);
                    mma16816(acc[mt][nt], al, bh[nt]);
                    mma16816(acc[mt][nt], ah, bl[nt]);
                }
            }
        }
    };

    const int steps = K >> 5;
    // ---- prologue: stage s=0 into buf 0 ----
    if (AMODE == 3) cpaA(0, 0); else loadA(0);
    cpaB(0, 0);
    CP_COMMIT();
    if (AMODE != 3) stsA(0);
    CP_WAIT0();
    __syncthreads();

    for (int s = 0; s < steps; ++s) {
        const int buf = s & 1, nbuf = buf ^ 1;
        const bool more = (s + 1 < steps);
        if (more) {
            if (AMODE == 3) cpaA(s + 1, nbuf); else loadA(s + 1);
            cpaB(s + 1, nbuf);
            CP_COMMIT();
        }
        domma(buf);
        if (more) {
            if (AMODE != 3) stsA(nbuf);
            CP_WAIT0();
            __syncthreads();
        }
    }

    // ---- epilogue ----
    const int r0base = m0 + wm * 64 + (lane >> 2);
    const int cbase  = n0 + wn * 32 + (lane & 3) * 2;
#pragma unroll
    for (int mt = 0; mt < 4; ++mt) {
#pragma unroll
        for (int nt = 0; nt < 4; ++nt) {
            const int cB = cbase + nt * 8;
            const float b0v = bias[cB], b1v = bias[cB + 1];
            float c0 = acc[mt][nt][0] + b0v, c1 = acc[mt][nt][1] + b1v;
            float c2 = acc[mt][nt][2] + b0v, c3 = acc[mt][nt][3] + b1v;
            if (RELU) {
                c0 = fmaxf(c0, 0.f); c1 = fmaxf(c1, 0.f);
                c2 = fmaxf(c2, 0.f); c3 = fmaxf(c3, 0.f);
            }
            const int gR0 = r0base + mt * 16, gR1 = gR0 + 8;
            if (OUTSPLIT == 0) {
                if (gR0 < M) *(float2*)(Cf + (size_t)gR0 * ldc + cB) = make_float2(c0, c1);
                if (gR1 < M) *(float2*)(Cf + (size_t)gR1 * ldc + cB) = make_float2(c2, c3);
            } else {
                uint32_t hp, lp;
                if (gR0 < M) {
                    split2(c0, c1, hp, lp);
                    *(uint32_t*)(Chi + (size_t)gR0 * ldc + cB) = hp;
                    *(uint32_t*)(Clo + (size_t)gR0 * ldc + cB) = lp;
                }
                if (gR1 < M) {
                    split2(c2, c3, hp, lp);
                    *(uint32_t*)(Chi + (size_t)gR1 * ldc + cB) = hp;
                    *(uint32_t*)(Clo + (size_t)gR1 * ldc + cB) = lp;
                }
            }
        }
    }
}

// ---------------- weight prep: transpose + hi/lo split ----------------
__global__ void split_weightT_kernel(const float* __restrict__ W, int K, int N,
                                     __nv_bfloat16* __restrict__ hi,
                                     __nv_bfloat16* __restrict__ lo)
{
    int i = blockIdx.x * blockDim.x + threadIdx.x;
    if (i >= K * N) return;
    int k = i / N, n = i % N;
    float v = W[i];
    __nv_bfloat16 h = __float2bfloat16(v);
    __nv_bfloat16 l = __float2bfloat16(v - __bfloat162float(h));
    hi[(size_t)n * K + k] = h;
    lo[(size_t)n * K + k] = l;
}

// ---------------- elementwise / glue kernels ----------------
__global__ void init_h_kernel(const int* __restrict__ nodes, const float* __restrict__ embed)
{
    int i = blockIdx.x * blockDim.x + threadIdx.x;
    if (i >= N_TOTAL * D) return;
    int row = i >> 7, c = i & 127;
    g_h[i] = embed[nodes[row / WINDOW] * D + c];
}
__global__ void edge_idx_kernel(const int* __restrict__ ie)
{
    int e = blockIdx.x * blockDim.x + threadIdx.x;
    if (e >= NE) return;
    int tt = ie[e * 3 + 0], s = ie[e * 3 + 1], d2 = ie[e * 3 + 2];
    g_nidx[e] = tt * N_NODES + s;
    g_midx[e] = tt * N_NODES + d2;
}
__global__ void zero_cnt_kernel()
{
    int i = blockIdx.x * blockDim.x + threadIdx.x;
    if (i < N_TOTAL) g_cnt[i] = 0;
}
__global__ void count_kernel()
{
    int e = blockIdx.x * blockDim.x + threadIdx.x;
    if (e < NE) atomicAdd(&g_cnt[g_midx[e]], 1);
}
__global__ void zero_agg_kernel()
{
    int i = blockIdx.x * blockDim.x + threadIdx.x;
    if (i < N_TOTAL * D) g_agg[i] = 0.f;
}
__global__ void scatter_kernel()
{
    int i = blockIdx.x * blockDim.x + threadIdx.x;
    if (i >= NE * D) return;
    int e = i >> 7, c = i & 127;
    atomicAdd(&g_agg[g_midx[e] * D + c], g_m[i]);
}
__global__ void mean_kernel()
{
    int i = blockIdx.x * blockDim.x + threadIdx.x;
    if (i >= N_TOTAL * D) return;
    int r = i >> 7;
    int c = g_cnt[r];
    g_agg[i] = (c > 0) ? g_agg[i] / (float)c : 0.f;
}
__global__ void temp_agg_kernel()
{
    int i = blockIdx.x * blockDim.x + threadIdx.x;
    if (i >= N_TOTAL * D) return;
    int v = i >> 7, c = i & 127;
    float s = 0.f; int n = 0;
    if (v >= N_NODES) { s += g_m[(v - N_NODES) * D + c]; n++; }
    if (v < TEDGE)    { s += g_m[(TEDGE + v) * D + c];   n++; }
    g_agg[i] = s / (float)n;
}
__device__ __forceinline__ float sigmoidf(float x) { return 1.f / (1.f + expf(-x)); }
__global__ void gru_kernel()
{
    int i = blockIdx.x * blockDim.x + threadIdx.x;
    if (i >= N_TOTAL * D) return;
    int r = i >> 7, c = i & 127;
    const float* xg = g_xg + (size_t)r * 384;
    const float* hg = g_hg + (size_t)r * 384;
    float z  = sigmoidf(xg[c]       + hg[c]);
    float rr = sigmoidf(xg[128 + c] + hg[128 + c]);
    float hc = tanhf(xg[256 + c] + rr * hg[256 + c]);
    float h = g_h[i];
    g_h[i] = z * h + (1.f - z) * hc;
}
__global__ void logits_softmax_kernel(const float* __restrict__ W3,
                                      const float* __restrict__ b3,
                                      float* __restrict__ out)
{
    const int row = blockIdx.x;
    const int w = threadIdx.x >> 5, lane = threadIdx.x & 31;
    __shared__ float lg[10];
    float s = 0.f;
    for (int k = lane; k < 512; k += 32)
        s += g_x2[(size_t)row * 512 + k] * W3[k * 10 + w];
#pragma unroll
    for (int o = 16; o; o >>= 1) s += __shfl_down_sync(0xffffffff, s, o);
    if (lane == 0) lg[w] = s + b3[w];
    __syncthreads();
    if (threadIdx.x == 0) {
        float mx = lg[0];
#pragma unroll
        for (int c = 1; c < 10; ++c) mx = fmaxf(mx, lg[c]);
        float e[10], sum = 0.f;
#pragma unroll
        for (int c = 0; c < 10; ++c) { e[c] = expf(lg[c] - mx); sum += e[c]; }
#pragma unroll
        for (int c = 0; c < 10; ++c) out[row * 10 + c] = e[c] / sum;
    }
}

// ---------------- host ----------------
extern "C" void kernel_launch(void* const* d_in, const int* in_sizes, int n_in,
                              void* d_out, int out_size)
{
    const int*   ie        = (const int*)  d_in[0];
    const int*   nodes     = (const int*)  d_in[1];
    const float* embed     = (const float*)d_in[2];
    const float* msg_W1    = (const float*)d_in[3];
    const float* msg_b1    = (const float*)d_in[4];
    const float* msg_W2    = (const float*)d_in[5];
    const float* msg_b2    = (const float*)d_in[6];
    const float* gru_int_W = (const float*)d_in[7];
    const float* gru_int_U = (const float*)d_in[8];
    const float* gru_int_b = (const float*)d_in[9];
    const float* gru_tmp_W = (const float*)d_in[10];
    const float* gru_tmp_U = (const float*)d_in[11];
    const float* gru_tmp_b = (const float*)d_in[12];
    const float* ro_W1     = (const float*)d_in[13];
    const float* ro_b1     = (const float*)d_in[14];
    const float* ro_W2     = (const float*)d_in[15];
    const float* ro_b2     = (const float*)d_in[16];
    const float* ro_W3     = (const float*)d_in[17];
    const float* ro_b3     = (const float*)d_in[18];
    float* out = (float*)d_out;

    float *h_p, *m_p, *agg_p, *xg_p, *hg_p, *x2_p, *P_p, *Q_p, *zero_p;
    int *nidx_p, *midx_p;
    __nv_bfloat16 *hidh_p, *hidl_p;
    __nv_bfloat16 *w1h, *w1l, *w2h, *w2l, *gih, *gil, *guh, *gul, *gth, *gtl, *gvh, *gvl, *r1h, *r1l, *r2h, *r2l;
    cudaGetSymbolAddress((void**)&h_p, g_h);
    cudaGetSymbolAddress((void**)&m_p, g_m);
    cudaGetSymbolAddress((void**)&agg_p, g_agg);
    cudaGetSymbolAddress((void**)&xg_p, g_xg);
    cudaGetSymbolAddress((void**)&hg_p, g_hg);
    cudaGetSymbolAddress((void**)&x2_p, g_x2);
    cudaGetSymbolAddress((void**)&P_p, g_P);
    cudaGetSymbolAddress((void**)&Q_p, g_Q);
    cudaGetSymbolAddress((void**)&zero_p, g_zero1024);
    cudaGetSymbolAddress((void**)&nidx_p, g_nidx);
    cudaGetSymbolAddress((void**)&midx_p, g_midx);
    cudaGetSymbolAddress((void**)&hidh_p, g_hid_hi);
    cudaGetSymbolAddress((void**)&hidl_p, g_hid_lo);
    cudaGetSymbolAddress((void**)&w1h, g_W1t_hi); cudaGetSymbolAddress((void**)&w1l, g_W1t_lo);
    cudaGetSymbolAddress((void**)&w2h, g_W2t_hi); cudaGetSymbolAddress((void**)&w2l, g_W2t_lo);
    cudaGetSymbolAddress((void**)&gih, g_GiW_hi); cudaGetSymbolAddress((void**)&gil, g_GiW_lo);
    cudaGetSymbolAddress((void**)&guh, g_GiU_hi); cudaGetSymbolAddress((void**)&gul, g_GiU_lo);
    cudaGetSymbolAddress((void**)&gth, g_GtW_hi); cudaGetSymbolAddress((void**)&gtl, g_GtW_lo);
    cudaGetSymbolAddress((void**)&gvh, g_GtU_hi); cudaGetSymbolAddress((void**)&gvl, g_GtU_lo);
    cudaGetSymbolAddress((void**)&r1h, g_R1t_hi); cudaGetSymbolAddress((void**)&r1l, g_R1t_lo);
    cudaGetSymbolAddress((void**)&r2h, g_R2t_hi); cudaGetSymbolAddress((void**)&r2l, g_R2t_lo);

    cudaFuncSetAttribute(hmma_gemm<0,0,0>, cudaFuncAttributeMaxDynamicSharedMemorySize, SMEM_BYTES);
    cudaFuncSetAttribute(hmma_gemm<0,1,1>, cudaFuncAttributeMaxDynamicSharedMemorySize, SMEM_BYTES);
    cudaFuncSetAttribute(hmma_gemm<3,0,1>, cudaFuncAttributeMaxDynamicSharedMemorySize, SMEM_BYTES);
    cudaFuncSetAttribute(hmma_gemm<4,0,1>, cudaFuncAttributeMaxDynamicSharedMemorySize, SMEM_BYTES);
    cudaFuncSetAttribute(hmma_gemm<5,0,1>, cudaFuncAttributeMaxDynamicSharedMemorySize, SMEM_BYTES);

    const int EL = 256;
    split_weightT_kernel<<<(256*HID + EL-1)/EL, EL>>>(msg_W1, 256, HID, w1h, w1l);
    split_weightT_kernel<<<(HID*D   + EL-1)/EL, EL>>>(msg_W2, HID, D,   w2h, w2l);
    split_weightT_kernel<<<(D*384   + EL-1)/EL, EL>>>(gru_int_W, D, 384, gih, gil);
    split_weightT_kernel<<<(D*384   + EL-1)/EL, EL>>>(gru_int_U, D, 384, guh, gul);
    split_weightT_kernel<<<(D*384   + EL-1)/EL, EL>>>(gru_tmp_W, D, 384, gth, gtl);
    split_weightT_kernel<<<(D*384   + EL-1)/EL, EL>>>(gru_tmp_U, D, 384, gvh, gvl);
    split_weightT_kernel<<<(D*HID   + EL-1)/EL, EL>>>(ro_W1, D, HID, r1h, r1l);
    split_weightT_kernel<<<(HID*512 + EL-1)/EL, EL>>>(ro_W2, HID, 512, r2h, r2l);

    init_h_kernel<<<(N_TOTAL*D + EL-1)/EL, EL>>>(nodes, embed);
    edge_idx_kernel<<<(NE + EL-1)/EL, EL>>>(ie);
    zero_cnt_kernel<<<(N_TOTAL + EL-1)/EL, EL>>>();
    count_kernel<<<(NE + EL-1)/EL, EL>>>();

    const int MT_E = NE / 128;                 // 1024
    const int MT_T = (TE2 + 127) / 128;        // 704
    const int MT_N = (N_TOTAL + 127) / 128;    // 391
    const int MT_R = (N_NODES + 127) / 128;    // 40

    for (int it = 0; it < 2; ++it) {
        // ---- interaction stage ----
        hmma_gemm<0,0,0><<<dim3(8, MT_N), 256, SMEM_BYTES>>>(
            h_p, nullptr, nullptr, nullptr, D, nullptr, nullptr,
            w1h, w1l, 256, msg_b1, P_p, nullptr, nullptr, HID, N_TOTAL, D);
        hmma_gemm<0,0,0><<<dim3(8, MT_N), 256, SMEM_BYTES>>>(
            h_p, nullptr, nullptr, nullptr, D, nullptr, nullptr,
            w1h + 128, w1l + 128, 256, zero_p, Q_p, nullptr, nullptr, HID, N_TOTAL, D);
        hmma_gemm<4,0,1><<<dim3(1, MT_E), 256, SMEM_BYTES>>>(
            P_p, Q_p, nullptr, nullptr, 0, nidx_p, midx_p,
            w2h, w2l, HID, msg_b2, m_p, nullptr, nullptr, D, NE, HID);
        zero_agg_kernel<<<(N_TOTAL*D + EL-1)/EL, EL>>>();
        scatter_kernel<<<(NE*D + EL-1)/EL, EL>>>();
        mean_kernel<<<(N_TOTAL*D + EL-1)/EL, EL>>>();
        hmma_gemm<0,0,0><<<dim3(3, MT_N), 256, SMEM_BYTES>>>(
            agg_p, nullptr, nullptr, nullptr, D, nullptr, nullptr,
            gih, gil, D, gru_int_b, xg_p, nullptr, nullptr, 384, N_TOTAL, D);
        hmma_gemm<0,0,0><<<dim3(3, MT_N), 256, SMEM_BYTES>>>(
            h_p, nullptr, nullptr, nullptr, D, nullptr, nullptr,
            guh, gul, D, gru_int_b + 384, hg_p, nullptr, nullptr, 384, N_TOTAL, D);
        gru_kernel<<<(N_TOTAL*D + EL-1)/EL, EL>>>();

        // ---- temporal stage ----
        hmma_gemm<0,0,0><<<dim3(8, MT_N), 256, SMEM_BYTES>>>(
            h_p, nullptr, nullptr, nullptr, D, nullptr, nullptr,
            w1h, w1l, 256, msg_b1, P_p, nullptr, nullptr, HID, N_TOTAL, D);
        hmma_gemm<0,0,0><<<dim3(8, MT_N), 256, SMEM_BYTES>>>(
            h_p, nullptr, nullptr, nullptr, D, nullptr, nullptr,
            w1h + 128, w1l + 128, 256, zero_p, Q_p, nullptr, nullptr, HID, N_TOTAL, D);
        hmma_gemm<5,0,1><<<dim3(1, MT_T), 256, SMEM_BYTES>>>(
            P_p, Q_p, nullptr, nullptr, 0, nullptr, nullptr,
            w2h, w2l, HID, msg_b2, m_p, nullptr, nullptr, D, TE2, HID);
        temp_agg_kernel<<<(N_TOTAL*D + EL-1)/EL, EL>>>();
        hmma_gemm<0,0,0><<<dim3(3, MT_N), 256, SMEM_BYTES>>>(
            agg_p, nullptr, nullptr, nullptr, D, nullptr, nullptr,
            gth, gtl, D, gru_tmp_b, xg_p, nullptr, nullptr, 384, N_TOTAL, D);
        hmma_gemm<0,0,0><<<dim3(3, MT_N), 256, SMEM_BYTES>>>(
            h_p, nullptr, nullptr, nullptr, D, nullptr, nullptr,
            gvh, gvl, D, gru_tmp_b + 384, hg_p, nullptr, nullptr, 384, N_TOTAL, D);
        gru_kernel<<<(N_TOTAL*D + EL-1)/EL, EL>>>();
    }

    // ---- readout ----
    hmma_gemm<0,1,1><<<dim3(8, MT_R), 256, SMEM_BYTES>>>(
        h_p, nullptr, nullptr, nullptr, D, nullptr, nullptr,
        r1h, r1l, D, ro_b1, nullptr, hidh_p, hidl_p, HID, N_NODES, D);
    hmma_gemm<3,0,1><<<dim3(4, MT_R), 256, SMEM_BYTES>>>(
        nullptr, nullptr, hidh_p, hidl_p, HID, nullptr, nullptr,
        r2h, r2l, HID, ro_b2, x2_p, nullptr, nullptr, 512, N_NODES, HID);
    logits_softmax_kernel<<<N_NODES, 320>>>(ro_W3, ro_b3, out);
}

// round 6
// speedup vs baseline: 3.3114x; 1.2897x over previous
#include <cuda_runtime.h>
#include <cuda_fp16.h>
#include <math.h>
#include <stdint.h>

#define D        128
#define N_NODES  5000
#define WINDOW   10
#define N_TOTAL  50000
#define NE       131072
#define HID      1024
#define TEDGE    45000
#define TE2      90000

// ---------------- device scratch (static, allocation-free) ----------------
__device__ __align__(16) float g_h[N_TOTAL * D];
__device__ __align__(16) float g_m[NE * D];
__device__ __align__(16) float g_agg[N_TOTAL * D];
__device__ __align__(16) float g_xg[N_TOTAL * 3 * D];
__device__ __align__(16) float g_hg[N_TOTAL * 3 * D];
__device__ int   g_cnt[N_TOTAL];
__device__ int   g_nidx[NE];
__device__ int   g_midx[NE];
__device__ __align__(16) float g_x2[N_NODES * 512];
__device__ __align__(16) float g_zero1024[1024];

// node-level msg-MLP layer-1 partials: P = h@W1_top + b1, Q = h@W1_bot
__device__ __align__(16) float g_P[(size_t)N_TOTAL * HID];
__device__ __align__(16) float g_Q[(size_t)N_TOTAL * HID];

// readout hidden, split hi/lo fp16
__device__ __align__(16) __half g_hid_hi[(size_t)N_NODES * HID];
__device__ __align__(16) __half g_hid_lo[(size_t)N_NODES * HID];

// transposed fp16 weights, layout [N][K]
__device__ __align__(16) __half g_W1t[HID * 256];
__device__ __align__(16) __half g_W2t[D * HID];
__device__ __align__(16) __half g_GiW[384 * D];
__device__ __align__(16) __half g_GiU[384 * D];
__device__ __align__(16) __half g_GtW[384 * D];
__device__ __align__(16) __half g_GtU[384 * D];
__device__ __align__(16) __half g_R1t[HID * D];
__device__ __align__(16) __half g_R2t[512 * HID];

// ---------------- helpers ----------------
__device__ __forceinline__ uint32_t smem_u32(const void* p) {
    uint32_t a;
    asm("{ .reg .u64 t; cvta.to.shared.u64 t, %1; cvt.u32.u64 %0, t; }" : "=r"(a) : "l"(p));
    return a;
}
__device__ __forceinline__ void ldsm4(uint32_t& r0, uint32_t& r1, uint32_t& r2, uint32_t& r3, uint32_t addr) {
    asm volatile("ldmatrix.sync.aligned.m8n8.x4.shared.b16 {%0,%1,%2,%3}, [%4];"
                 : "=r"(r0), "=r"(r1), "=r"(r2), "=r"(r3) : "r"(addr));
}
__device__ __forceinline__ void mma16816(float* c, const uint32_t* a, const uint32_t* b) {
    asm volatile("mma.sync.aligned.m16n8k16.row.col.f32.f16.f16.f32 "
                 "{%0,%1,%2,%3}, {%4,%5,%6,%7}, {%8,%9}, {%0,%1,%2,%3};"
                 : "+f"(c[0]), "+f"(c[1]), "+f"(c[2]), "+f"(c[3])
                 : "r"(a[0]), "r"(a[1]), "r"(a[2]), "r"(a[3]), "r"(b[0]), "r"(b[1]));
}
__device__ __forceinline__ void cp16(uint32_t saddr, const void* g) {
    asm volatile("cp.async.cg.shared.global [%0], [%1], 16;" :: "r"(saddr), "l"(g));
}
#define CP_COMMIT() asm volatile("cp.async.commit_group;" ::: "memory")
#define CP_WAIT0()  asm volatile("cp.async.wait_group 0;" ::: "memory")

// split fp32 pair into packed fp16 hi / lo
__device__ __forceinline__ void split2(float x, float y, uint32_t& h, uint32_t& l) {
    __half hx = __float2half_rn(x);
    __half hy = __float2half_rn(y);
    __half lx = __float2half_rn(x - __half2float(hx));
    __half ly = __float2half_rn(y - __half2float(hy));
    h = ((uint32_t)__half_as_ushort(hy) << 16) | (uint32_t)__half_as_ushort(hx);
    l = ((uint32_t)__half_as_ushort(ly) << 16) | (uint32_t)__half_as_ushort(lx);
}

// ---------------- fp16 2-term HMMA GEMM, double-buffered ----------------
// C = act( A'[M,K] @ W[K,N] + bias );  A split hi/lo fp16, W single fp16 [N][ldb].
// AMODE 0: A fp32 row-major stride lda
// AMODE 3: A pre-split fp16 hi/lo (cp.async)
// AMODE 4: A[r,k] = relu(P[nidx[r]][k] + Q[midx[r]][k])
// AMODE 5: same with analytic temporal indices
#define ASTR   56
#define PANEL  (128 * ASTR)
#define PANELB (PANEL * 2)               // 14336 B
#define BUF_BYTES (3 * PANELB)           // 43008 (Ahi, Alo, B)
#define SMEM_BYTES (2 * BUF_BYTES)       // 86016

template<int AMODE, int OUTSPLIT, int RELU>
__global__ __launch_bounds__(256, 2)
void hmma_gemm(const float* __restrict__ Af,
               const float* __restrict__ Qf,
               const __half* __restrict__ Ahi_g,
               const __half* __restrict__ Alo_g,
               int lda,
               const int* __restrict__ idxA, const int* __restrict__ idxB,
               const __half* __restrict__ Bw,
               int ldb,
               const float* __restrict__ bias,
               float* __restrict__ Cf,
               __half* __restrict__ Chi, __half* __restrict__ Clo,
               int ldc, int M, int K)
{
    extern __shared__ __half smbuf[];
    const uint32_t sbase = smem_u32(smbuf);

    const int t = threadIdx.x, lane = t & 31, w = t >> 5;
    const int wm = w >> 2, wn = w & 3;
    const int m0 = blockIdx.y * 128, n0 = blockIdx.x * 128;
    const int lrow = t >> 1, lhalf = t & 1;
    const uint32_t arow_off = ((uint32_t)(lrow * ASTR + lhalf * 16)) << 1;

    float acc[4][4][4];
#pragma unroll
    for (int i = 0; i < 4; ++i)
#pragma unroll
        for (int j = 0; j < 4; ++j)
#pragma unroll
            for (int q = 0; q < 4; ++q) acc[i][j][q] = 0.f;

    uint32_t rh[8], rl[8];

    auto loadA = [&](int s) {
        if (AMODE == 3) return;
        const int k0 = s << 5;
        int gRow = m0 + lrow; if (gRow >= M) gRow = M - 1;
        float vv[16];
        if (AMODE == 0) {
            const float* src = Af + (size_t)gRow * lda + k0 + lhalf * 16;
#pragma unroll
            for (int i = 0; i < 16; i += 4) {
                float4 v = *(const float4*)(src + i);
                vv[i] = v.x; vv[i+1] = v.y; vv[i+2] = v.z; vv[i+3] = v.w;
            }
        } else {
            int n_, m_;
            if (AMODE == 4) { n_ = idxA[gRow]; m_ = idxB[gRow]; }
            else {
                if (gRow < TEDGE) { n_ = gRow;                   m_ = gRow + N_NODES; }
                else              { n_ = gRow - TEDGE + N_NODES; m_ = gRow - TEDGE;   }
            }
            const float* p = Af + (size_t)n_ * HID + k0 + lhalf * 16;
            const float* q = Qf + (size_t)m_ * HID + k0 + lhalf * 16;
#pragma unroll
            for (int i = 0; i < 16; i += 4) {
                float4 a = *(const float4*)(p + i);
                float4 b = *(const float4*)(q + i);
                vv[i]   = fmaxf(a.x + b.x, 0.f);
                vv[i+1] = fmaxf(a.y + b.y, 0.f);
                vv[i+2] = fmaxf(a.z + b.z, 0.f);
                vv[i+3] = fmaxf(a.w + b.w, 0.f);
            }
        }
#pragma unroll
        for (int i = 0; i < 8; ++i) split2(vv[2*i], vv[2*i+1], rh[i], rl[i]);
    };
    auto stsA = [&](int buf) {
        if (AMODE == 3) return;
        __half* base = smbuf + (size_t)buf * (BUF_BYTES / 2);
        __half* dh = base + lrow * ASTR + lhalf * 16;
        __half* dl = dh + PANEL;
        *(uint4*)dh       = make_uint4(rh[0], rh[1], rh[2], rh[3]);
        *(uint4*)(dh + 8) = make_uint4(rh[4], rh[5], rh[6], rh[7]);
        *(uint4*)dl       = make_uint4(rl[0], rl[1], rl[2], rl[3]);
        *(uint4*)(dl + 8) = make_uint4(rl[4], rl[5], rl[6], rl[7]);
    };
    auto cpaA = [&](int s, int buf) {   // AMODE 3
        const int k0 = s << 5;
        int gRow = m0 + lrow; if (gRow >= M) gRow = M - 1;
        const size_t off = (size_t)gRow * lda + k0 + lhalf * 16;
        const uint32_t d = sbase + buf * BUF_BYTES + arow_off;
        cp16(d,      Ahi_g + off);
        cp16(d + 16, Ahi_g + off + 8);
        cp16(d + PANELB,      Alo_g + off);
        cp16(d + PANELB + 16, Alo_g + off + 8);
    };
    auto cpaB = [&](int s, int buf) {
        const int k0 = s << 5;
        const size_t off = (size_t)(n0 + lrow) * ldb + k0 + lhalf * 16;
        const uint32_t d = sbase + buf * BUF_BYTES + 2 * PANELB + arow_off;
        cp16(d,      Bw + off);
        cp16(d + 16, Bw + off + 8);
    };
    auto domma = [&](int buf) {
        const uint32_t bb = sbase + buf * BUF_BYTES;
#pragma unroll
        for (int kk = 0; kk < 2; ++kk) {
            const int kc = kk * 16;
            uint32_t bh[4][2];
#pragma unroll
            for (int p = 0; p < 2; ++p) {
                const uint32_t boff =
                    ((uint32_t)((wn * 32 + p * 16 + ((lane >> 4) << 3) + (lane & 7)) * ASTR
                                + kc + (((lane >> 3) & 1) << 3))) << 1;
                uint32_t r0, r1, r2, r3;
                ldsm4(r0, r1, r2, r3, bb + 2 * PANELB + boff);
                bh[p * 2][0] = r0; bh[p * 2][1] = r1; bh[p * 2 + 1][0] = r2; bh[p * 2 + 1][1] = r3;
            }
#pragma unroll
            for (int mt = 0; mt < 4; ++mt) {
                const uint32_t aoff =
                    ((uint32_t)((wm * 64 + mt * 16 + (lane & 15)) * ASTR + kc + ((lane >> 4) << 3))) << 1;
                uint32_t ah[4], al[4];
                ldsm4(ah[0], ah[1], ah[2], ah[3], bb + aoff);
                ldsm4(al[0], al[1], al[2], al[3], bb + PANELB + aoff);
#pragma unroll
                for (int nt = 0; nt < 4; ++nt) {
                    mma16816(acc[mt][nt], ah, bh[nt]);
                    mma16816(acc[mt][nt], al, bh[nt]);
                }
            }
        }
    };

    const int steps = K >> 5;
    if (AMODE == 3) cpaA(0, 0); else loadA(0);
    cpaB(0, 0);
    CP_COMMIT();
    if (AMODE != 3) stsA(0);
    CP_WAIT0();
    __syncthreads();

    for (int s = 0; s < steps; ++s) {
        const int buf = s & 1, nbuf = buf ^ 1;
        const bool more = (s + 1 < steps);
        if (more) {
            if (AMODE == 3) cpaA(s + 1, nbuf); else loadA(s + 1);
            cpaB(s + 1, nbuf);
            CP_COMMIT();
        }
        domma(buf);
        if (more) {
            if (AMODE != 3) stsA(nbuf);
            CP_WAIT0();
            __syncthreads();
        }
    }

    // ---- epilogue ----
    const int r0base = m0 + wm * 64 + (lane >> 2);
    const int cbase  = n0 + wn * 32 + (lane & 3) * 2;
#pragma unroll
    for (int mt = 0; mt < 4; ++mt) {
#pragma unroll
        for (int nt = 0; nt < 4; ++nt) {
            const int cB = cbase + nt * 8;
            const float b0v = bias[cB], b1v = bias[cB + 1];
            float c0 = acc[mt][nt][0] + b0v, c1 = acc[mt][nt][1] + b1v;
            float c2 = acc[mt][nt][2] + b0v, c3 = acc[mt][nt][3] + b1v;
            if (RELU) {
                c0 = fmaxf(c0, 0.f); c1 = fmaxf(c1, 0.f);
                c2 = fmaxf(c2, 0.f); c3 = fmaxf(c3, 0.f);
            }
            const int gR0 = r0base + mt * 16, gR1 = gR0 + 8;
            if (OUTSPLIT == 0) {
                if (gR0 < M) *(float2*)(Cf + (size_t)gR0 * ldc + cB) = make_float2(c0, c1);
                if (gR1 < M) *(float2*)(Cf + (size_t)gR1 * ldc + cB) = make_float2(c2, c3);
            } else {
                uint32_t hp, lp;
                if (gR0 < M) {
                    split2(c0, c1, hp, lp);
                    *(uint32_t*)(Chi + (size_t)gR0 * ldc + cB) = hp;
                    *(uint32_t*)(Clo + (size_t)gR0 * ldc + cB) = lp;
                }
                if (gR1 < M) {
                    split2(c2, c3, hp, lp);
                    *(uint32_t*)(Chi + (size_t)gR1 * ldc + cB) = hp;
                    *(uint32_t*)(Clo + (size_t)gR1 * ldc + cB) = lp;
                }
            }
        }
    }
}

// ---------------- weight prep: transpose + fp16 convert ----------------
__global__ void cvt_weightT_kernel(const float* __restrict__ W, int K, int N,
                                   __half* __restrict__ o)
{
    int i = blockIdx.x * blockDim.x + threadIdx.x;
    if (i >= K * N) return;
    int k = i / N, n = i % N;
    o[(size_t)n * K + k] = __float2half_rn(W[i]);
}

// ---------------- elementwise / glue kernels ----------------
__global__ void init_h_kernel(const int* __restrict__ nodes, const float* __restrict__ embed)
{
    int i = blockIdx.x * blockDim.x + threadIdx.x;
    if (i >= N_TOTAL * D) return;
    int row = i >> 7, c = i & 127;
    g_h[i] = embed[nodes[row / WINDOW] * D + c];
}
__global__ void edge_idx_kernel(const int* __restrict__ ie)
{
    int e = blockIdx.x * blockDim.x + threadIdx.x;
    if (e >= NE) return;
    int tt = ie[e * 3 + 0], s = ie[e * 3 + 1], d2 = ie[e * 3 + 2];
    g_nidx[e] = tt * N_NODES + s;
    g_midx[e] = tt * N_NODES + d2;
}
__global__ void zero_cnt_kernel()
{
    int i = blockIdx.x * blockDim.x + threadIdx.x;
    if (i < N_TOTAL) g_cnt[i] = 0;
}
__global__ void count_kernel()
{
    int e = blockIdx.x * blockDim.x + threadIdx.x;
    if (e < NE) atomicAdd(&g_cnt[g_midx[e]], 1);
}
__global__ void zero_agg_kernel()
{
    int i = blockIdx.x * blockDim.x + threadIdx.x;
    if (i < N_TOTAL * D) g_agg[i] = 0.f;
}
__global__ void scatter_kernel()
{
    int i = blockIdx.x * blockDim.x + threadIdx.x;
    if (i >= NE * D) return;
    int e = i >> 7, c = i & 127;
    atomicAdd(&g_agg[g_midx[e] * D + c], g_m[i]);
}
__global__ void mean_kernel()
{
    int i = blockIdx.x * blockDim.x + threadIdx.x;
    if (i >= N_TOTAL * D) return;
    int r = i >> 7;
    int c = g_cnt[r];
    g_agg[i] = (c > 0) ? g_agg[i] / (float)c : 0.f;
}
__global__ void temp_agg_kernel()
{
    int i = blockIdx.x * blockDim.x + threadIdx.x;
    if (i >= N_TOTAL * D) return;
    int v = i >> 7, c = i & 127;
    float s = 0.f; int n = 0;
    if (v >= N_NODES) { s += g_m[(v - N_NODES) * D + c]; n++; }
    if (v < TEDGE)    { s += g_m[(TEDGE + v) * D + c];   n++; }
    g_agg[i] = s / (float)n;
}
__device__ __forceinline__ float sigmoidf(float x) { return 1.f / (1.f + expf(-x)); }
__global__ void gru_kernel()
{
    int i = blockIdx.x * blockDim.x + threadIdx.x;
    if (i >= N_TOTAL * D) return;
    int r = i >> 7, c = i & 127;
    const float* xg = g_xg + (size_t)r * 384;
    const float* hg = g_hg + (size_t)r * 384;
    float z  = sigmoidf(xg[c]       + hg[c]);
    float rr = sigmoidf(xg[128 + c] + hg[128 + c]);
    float hc = tanhf(xg[256 + c] + rr * hg[256 + c]);
    float h = g_h[i];
    g_h[i] = z * h + (1.f - z) * hc;
}
__global__ void logits_softmax_kernel(const float* __restrict__ W3,
                                      const float* __restrict__ b3,
                                      float* __restrict__ out)
{
    const int row = blockIdx.x;
    const int w = threadIdx.x >> 5, lane = threadIdx.x & 31;
    __shared__ float lg[10];
    float s = 0.f;
    for (int k = lane; k < 512; k += 32)
        s += g_x2[(size_t)row * 512 + k] * W3[k * 10 + w];
#pragma unroll
    for (int o = 16; o; o >>= 1) s += __shfl_down_sync(0xffffffff, s, o);
    if (lane == 0) lg[w] = s + b3[w];
    __syncthreads();
    if (threadIdx.x == 0) {
        float mx = lg[0];
#pragma unroll
        for (int c = 1; c < 10; ++c) mx = fmaxf(mx, lg[c]);
        float e[10], sum = 0.f;
#pragma unroll
        for (int c = 0; c < 10; ++c) { e[c] = expf(lg[c] - mx); sum += e[c]; }
#pragma unroll
        for (int c = 0; c < 10; ++c) out[row * 10 + c] = e[c] / sum;
    }
}

// ---------------- host ----------------
extern "C" void kernel_launch(void* const* d_in, const int* in_sizes, int n_in,
                              void* d_out, int out_size)
{
    const int*   ie        = (const int*)  d_in[0];
    const int*   nodes     = (const int*)  d_in[1];
    const float* embed     = (const float*)d_in[2];
    const float* msg_W1    = (const float*)d_in[3];
    const float* msg_b1    = (const float*)d_in[4];
    const float* msg_W2    = (const float*)d_in[5];
    const float* msg_b2    = (const float*)d_in[6];
    const float* gru_int_W = (const float*)d_in[7];
    const float* gru_int_U = (const float*)d_in[8];
    const float* gru_int_b = (const float*)d_in[9];
    const float* gru_tmp_W = (const float*)d_in[10];
    const float* gru_tmp_U = (const float*)d_in[11];
    const float* gru_tmp_b = (const float*)d_in[12];
    const float* ro_W1     = (const float*)d_in[13];
    const float* ro_b1     = (const float*)d_in[14];
    const float* ro_W2     = (const float*)d_in[15];
    const float* ro_b2     = (const float*)d_in[16];
    const float* ro_W3     = (const float*)d_in[17];
    const float* ro_b3     = (const float*)d_in[18];
    float* out = (float*)d_out;

    float *h_p, *m_p, *agg_p, *xg_p, *hg_p, *x2_p, *P_p, *Q_p, *zero_p;
    int *nidx_p, *midx_p;
    __half *hidh_p, *hidl_p;
    __half *w1, *w2, *gi, *gu, *gt, *gv, *r1, *r2;
    cudaGetSymbolAddress((void**)&h_p, g_h);
    cudaGetSymbolAddress((void**)&m_p, g_m);
    cudaGetSymbolAddress((void**)&agg_p, g_agg);
    cudaGetSymbolAddress((void**)&xg_p, g_xg);
    cudaGetSymbolAddress((void**)&hg_p, g_hg);
    cudaGetSymbolAddress((void**)&x2_p, g_x2);
    cudaGetSymbolAddress((void**)&P_p, g_P);
    cudaGetSymbolAddress((void**)&Q_p, g_Q);
    cudaGetSymbolAddress((void**)&zero_p, g_zero1024);
    cudaGetSymbolAddress((void**)&nidx_p, g_nidx);
    cudaGetSymbolAddress((void**)&midx_p, g_midx);
    cudaGetSymbolAddress((void**)&hidh_p, g_hid_hi);
    cudaGetSymbolAddress((void**)&hidl_p, g_hid_lo);
    cudaGetSymbolAddress((void**)&w1, g_W1t);
    cudaGetSymbolAddress((void**)&w2, g_W2t);
    cudaGetSymbolAddress((void**)&gi, g_GiW);
    cudaGetSymbolAddress((void**)&gu, g_GiU);
    cudaGetSymbolAddress((void**)&gt, g_GtW);
    cudaGetSymbolAddress((void**)&gv, g_GtU);
    cudaGetSymbolAddress((void**)&r1, g_R1t);
    cudaGetSymbolAddress((void**)&r2, g_R2t);

    cudaFuncSetAttribute(hmma_gemm<0,0,0>, cudaFuncAttributeMaxDynamicSharedMemorySize, SMEM_BYTES);
    cudaFuncSetAttribute(hmma_gemm<0,1,1>, cudaFuncAttributeMaxDynamicSharedMemorySize, SMEM_BYTES);
    cudaFuncSetAttribute(hmma_gemm<3,0,1>, cudaFuncAttributeMaxDynamicSharedMemorySize, SMEM_BYTES);
    cudaFuncSetAttribute(hmma_gemm<4,0,1>, cudaFuncAttributeMaxDynamicSharedMemorySize, SMEM_BYTES);
    cudaFuncSetAttribute(hmma_gemm<5,0,1>, cudaFuncAttributeMaxDynamicSharedMemorySize, SMEM_BYTES);

    const int EL = 256;
    cvt_weightT_kernel<<<(256*HID + EL-1)/EL, EL>>>(msg_W1, 256, HID, w1);
    cvt_weightT_kernel<<<(HID*D   + EL-1)/EL, EL>>>(msg_W2, HID, D,   w2);
    cvt_weightT_kernel<<<(D*384   + EL-1)/EL, EL>>>(gru_int_W, D, 384, gi);
    cvt_weightT_kernel<<<(D*384   + EL-1)/EL, EL>>>(gru_int_U, D, 384, gu);
    cvt_weightT_kernel<<<(D*384   + EL-1)/EL, EL>>>(gru_tmp_W, D, 384, gt);
    cvt_weightT_kernel<<<(D*384   + EL-1)/EL, EL>>>(gru_tmp_U, D, 384, gv);
    cvt_weightT_kernel<<<(D*HID   + EL-1)/EL, EL>>>(ro_W1, D, HID, r1);
    cvt_weightT_kernel<<<(HID*512 + EL-1)/EL, EL>>>(ro_W2, HID, 512, r2);

    init_h_kernel<<<(N_TOTAL*D + EL-1)/EL, EL>>>(nodes, embed);
    edge_idx_kernel<<<(NE + EL-1)/EL, EL>>>(ie);
    zero_cnt_kernel<<<(N_TOTAL + EL-1)/EL, EL>>>();
    count_kernel<<<(NE + EL-1)/EL, EL>>>();

    const int MT_E = NE / 128;
    const int MT_T = (TE2 + 127) / 128;
    const int MT_N = (N_TOTAL + 127) / 128;
    const int MT_R = (N_NODES + 127) / 128;

    for (int it = 0; it < 2; ++it) {
        // ---- interaction stage ----
        hmma_gemm<0,0,0><<<dim3(8, MT_N), 256, SMEM_BYTES>>>(
            h_p, nullptr, nullptr, nullptr, D, nullptr, nullptr,
            w1, 256, msg_b1, P_p, nullptr, nullptr, HID, N_TOTAL, D);
        hmma_gemm<0,0,0><<<dim3(8, MT_N), 256, SMEM_BYTES>>>(
            h_p, nullptr, nullptr, nullptr, D, nullptr, nullptr,
            w1 + 128, 256, zero_p, Q_p, nullptr, nullptr, HID, N_TOTAL, D);
        hmma_gemm<4,0,1><<<dim3(1, MT_E), 256, SMEM_BYTES>>>(
            P_p, Q_p, nullptr, nullptr, 0, nidx_p, midx_p,
            w2, HID, msg_b2, m_p, nullptr, nullptr, D, NE, HID);
        zero_agg_kernel<<<(N_TOTAL*D + EL-1)/EL, EL>>>();
        scatter_kernel<<<(NE*D + EL-1)/EL, EL>>>();
        mean_kernel<<<(N_TOTAL*D + EL-1)/EL, EL>>>();
        hmma_gemm<0,0,0><<<dim3(3, MT_N), 256, SMEM_BYTES>>>(
            agg_p, nullptr, nullptr, nullptr, D, nullptr, nullptr,
            gi, D, gru_int_b, xg_p, nullptr, nullptr, 384, N_TOTAL, D);
        hmma_gemm<0,0,0><<<dim3(3, MT_N), 256, SMEM_BYTES>>>(
            h_p, nullptr, nullptr, nullptr, D, nullptr, nullptr,
            gu, D, gru_int_b + 384, hg_p, nullptr, nullptr, 384, N_TOTAL, D);
        gru_kernel<<<(N_TOTAL*D + EL-1)/EL, EL>>>();

        // ---- temporal stage ----
        hmma_gemm<0,0,0><<<dim3(8, MT_N), 256, SMEM_BYTES>>>(
            h_p, nullptr, nullptr, nullptr, D, nullptr, nullptr,
            w1, 256, msg_b1, P_p, nullptr, nullptr, HID, N_TOTAL, D);
        hmma_gemm<0,0,0><<<dim3(8, MT_N), 256, SMEM_BYTES>>>(
            h_p, nullptr, nullptr, nullptr, D, nullptr, nullptr,
            w1 + 128, 256, zero_p, Q_p, nullptr, nullptr, HID, N_TOTAL, D);
        hmma_gemm<5,0,1><<<dim3(1, MT_T), 256, SMEM_BYTES>>>(
            P_p, Q_p, nullptr, nullptr, 0, nullptr, nullptr,
            w2, HID, msg_b2, m_p, nullptr, nullptr, D, TE2, HID);
        temp_agg_kernel<<<(N_TOTAL*D + EL-1)/EL, EL>>>();
        hmma_gemm<0,0,0><<<dim3(3, MT_N), 256, SMEM_BYTES>>>(
            agg_p, nullptr, nullptr, nullptr, D, nullptr, nullptr,
            gt, D, gru_tmp_b, xg_p, nullptr, nullptr, 384, N_TOTAL, D);
        hmma_gemm<0,0,0><<<dim3(3, MT_N), 256, SMEM_BYTES>>>(
            h_p, nullptr, nullptr, nullptr, D, nullptr, nullptr,
            gv, D, gru_tmp_b + 384, hg_p, nullptr, nullptr, 384, N_TOTAL, D);
        gru_kernel<<<(N_TOTAL*D + EL-1)/EL, EL>>>();
    }

    // ---- readout ----
    hmma_gemm<0,1,1><<<dim3(8, MT_R), 256, SMEM_BYTES>>>(
        h_p, nullptr, nullptr, nullptr, D, nullptr, nullptr,
        r1, D, ro_b1, nullptr, hidh_p, hidl_p, HID, N_NODES, D);
    hmma_gemm<3,0,1><<<dim3(4, MT_R), 256, SMEM_BYTES>>>(
        nullptr, nullptr, hidh_p, hidl_p, HID, nullptr, nullptr,
        r2, HID, ro_b2, x2_p, nullptr, nullptr, 512, N_NODES, HID);
    logits_softmax_kernel<<<N_NODES, 320>>>(ro_W3, ro_b3, out);
}

// round 7
// speedup vs baseline: 4.0636x; 1.2272x over previous
#include <cuda_runtime.h>
#include <cuda_fp16.h>
#include <math.h>
#include <stdint.h>

#define D        128
#define N_NODES  5000
#define WINDOW   10
#define N_TOTAL  50000
#define NE       131072
#define HID      1024
#define TEDGE    45000
#define TE2      90000

// ---------------- device scratch ----------------
__device__ __align__(16) float g_h[N_TOTAL * D];
__device__ __align__(16) float g_m[NE * D];
__device__ __align__(16) float g_agg[N_TOTAL * D];
__device__ __align__(16) float g_xg[N_TOTAL * 3 * D];
__device__ __align__(16) float g_hg[N_TOTAL * 3 * D];
__device__ int   g_cnt[N_TOTAL];
__device__ int   g_nidx[NE];
__device__ int   g_midx[NE];
__device__ __align__(16) float g_x2[N_NODES * 512];
__device__ __align__(16) float g_zero1024[1024];

__device__ __align__(16) float g_P[(size_t)N_TOTAL * HID];
__device__ __align__(16) float g_Q[(size_t)N_TOTAL * HID];

// readout hidden, single fp16
__device__ __align__(16) __half g_hid[(size_t)N_NODES * HID];

// transposed fp16 weights, layout [N][K]
__device__ __align__(16) __half g_W1t[HID * 256];
__device__ __align__(16) __half g_W2t[D * HID];
__device__ __align__(16) __half g_GiW[384 * D];
__device__ __align__(16) __half g_GiU[384 * D];
__device__ __align__(16) __half g_GtW[384 * D];
__device__ __align__(16) __half g_GtU[384 * D];
__device__ __align__(16) __half g_R1t[HID * D];
__device__ __align__(16) __half g_R2t[512 * HID];

// ---------------- helpers ----------------
__device__ __forceinline__ uint32_t smem_u32(const void* p) {
    uint32_t a;
    asm("{ .reg .u64 t; cvta.to.shared.u64 t, %1; cvt.u32.u64 %0, t; }" : "=r"(a) : "l"(p));
    return a;
}
__device__ __forceinline__ void ldsm4(uint32_t& r0, uint32_t& r1, uint32_t& r2, uint32_t& r3, uint32_t addr) {
    asm volatile("ldmatrix.sync.aligned.m8n8.x4.shared.b16 {%0,%1,%2,%3}, [%4];"
                 : "=r"(r0), "=r"(r1), "=r"(r2), "=r"(r3) : "r"(addr));
}
__device__ __forceinline__ void mma16816(float* c, const uint32_t* a, const uint32_t* b) {
    asm volatile("mma.sync.aligned.m16n8k16.row.col.f32.f16.f16.f32 "
                 "{%0,%1,%2,%3}, {%4,%5,%6,%7}, {%8,%9}, {%0,%1,%2,%3};"
                 : "+f"(c[0]), "+f"(c[1]), "+f"(c[2]), "+f"(c[3])
                 : "r"(a[0]), "r"(a[1]), "r"(a[2]), "r"(a[3]), "r"(b[0]), "r"(b[1]));
}
__device__ __forceinline__ void cp16(uint32_t saddr, const void* g) {
    asm volatile("cp.async.cg.shared.global [%0], [%1], 16;" :: "r"(saddr), "l"(g));
}
#define CP_COMMIT() asm volatile("cp.async.commit_group;" ::: "memory")
#define CP_WAIT0()  asm volatile("cp.async.wait_group 0;" ::: "memory")

__device__ __forceinline__ uint32_t pack_h2(float x, float y) {
    __half2 h = __floats2half2_rn(x, y);
    return *(uint32_t*)&h;
}

// ---------------- fp16 HMMA GEMM, double-buffered ----------------
// C = act( A'[M,K] @ W[K,N] + bias );  A fp16 (converted on load), W fp16 [N][ldb].
// AMODE 0: A fp32 row-major stride lda
// AMODE 3: A fp16 row-major stride lda (cp.async)
// AMODE 4: A[r,k] = relu(P[nidx[r]][k] + Q[midx[r]][k])
// AMODE 5: same with analytic temporal indices
// OUTSPLIT 0: fp32 to Cf; OUTSPLIT 1: fp16 to Chi.
#define ASTR   56
#define PANEL  (128 * ASTR)
#define PANELB (PANEL * 2)               // 14336 B
#define BUF_BYTES (2 * PANELB)           // 28672 (A, B)
#define SMEM_BYTES (2 * BUF_BYTES)       // 57344

template<int AMODE, int OUTSPLIT, int RELU>
__global__ __launch_bounds__(256, 2)
void hmma_gemm(const float* __restrict__ Af,
               const float* __restrict__ Qf,
               const __half* __restrict__ Ah_g,
               int lda,
               const int* __restrict__ idxA, const int* __restrict__ idxB,
               const __half* __restrict__ Bw,
               int ldb,
               const float* __restrict__ bias,
               float* __restrict__ Cf,
               __half* __restrict__ Chi,
               int ldc, int M, int K)
{
    extern __shared__ __half smbuf[];
    const uint32_t sbase = smem_u32(smbuf);

    const int t = threadIdx.x, lane = t & 31, w = t >> 5;
    const int wm = w >> 2, wn = w & 3;
    const int m0 = blockIdx.y * 128, n0 = blockIdx.x * 128;
    const int lrow = t >> 1, lhalf = t & 1;
    const uint32_t arow_off = ((uint32_t)(lrow * ASTR + lhalf * 16)) << 1;

    float acc[4][4][4];
#pragma unroll
    for (int i = 0; i < 4; ++i)
#pragma unroll
        for (int j = 0; j < 4; ++j)
#pragma unroll
            for (int q = 0; q < 4; ++q) acc[i][j][q] = 0.f;

    uint32_t rh[8];

    auto loadA = [&](int s) {
        if (AMODE == 3) return;
        const int k0 = s << 5;
        int gRow = m0 + lrow; if (gRow >= M) gRow = M - 1;
        float vv[16];
        if (AMODE == 0) {
            const float* src = Af + (size_t)gRow * lda + k0 + lhalf * 16;
#pragma unroll
            for (int i = 0; i < 16; i += 4) {
                float4 v = *(const float4*)(src + i);
                vv[i] = v.x; vv[i+1] = v.y; vv[i+2] = v.z; vv[i+3] = v.w;
            }
        } else {
            int n_, m_;
            if (AMODE == 4) { n_ = idxA[gRow]; m_ = idxB[gRow]; }
            else {
                if (gRow < TEDGE) { n_ = gRow;                   m_ = gRow + N_NODES; }
                else              { n_ = gRow - TEDGE + N_NODES; m_ = gRow - TEDGE;   }
            }
            const float* p = Af + (size_t)n_ * HID + k0 + lhalf * 16;
            const float* q = Qf + (size_t)m_ * HID + k0 + lhalf * 16;
#pragma unroll
            for (int i = 0; i < 16; i += 4) {
                float4 a = *(const float4*)(p + i);
                float4 b = *(const float4*)(q + i);
                vv[i]   = fmaxf(a.x + b.x, 0.f);
                vv[i+1] = fmaxf(a.y + b.y, 0.f);
                vv[i+2] = fmaxf(a.z + b.z, 0.f);
                vv[i+3] = fmaxf(a.w + b.w, 0.f);
            }
        }
#pragma unroll
        for (int i = 0; i < 8; ++i) rh[i] = pack_h2(vv[2*i], vv[2*i+1]);
    };
    auto stsA = [&](int buf) {
        if (AMODE == 3) return;
        __half* dh = smbuf + (size_t)buf * (BUF_BYTES / 2) + lrow * ASTR + lhalf * 16;
        *(uint4*)dh       = make_uint4(rh[0], rh[1], rh[2], rh[3]);
        *(uint4*)(dh + 8) = make_uint4(rh[4], rh[5], rh[6], rh[7]);
    };
    auto cpaA = [&](int s, int buf) {   // AMODE 3
        const int k0 = s << 5;
        int gRow = m0 + lrow; if (gRow >= M) gRow = M - 1;
        const size_t off = (size_t)gRow * lda + k0 + lhalf * 16;
        const uint32_t d = sbase + buf * BUF_BYTES + arow_off;
        cp16(d,      Ah_g + off);
        cp16(d + 16, Ah_g + off + 8);
    };
    auto cpaB = [&](int s, int buf) {
        const int k0 = s << 5;
        const size_t off = (size_t)(n0 + lrow) * ldb + k0 + lhalf * 16;
        const uint32_t d = sbase + buf * BUF_BYTES + PANELB + arow_off;
        cp16(d,      Bw + off);
        cp16(d + 16, Bw + off + 8);
    };
    auto domma = [&](int buf) {
        const uint32_t bb = sbase + buf * BUF_BYTES;
#pragma unroll
        for (int kk = 0; kk < 2; ++kk) {
            const int kc = kk * 16;
            uint32_t bh[4][2];
#pragma unroll
            for (int p = 0; p < 2; ++p) {
                const uint32_t boff =
                    ((uint32_t)((wn * 32 + p * 16 + ((lane >> 4) << 3) + (lane & 7)) * ASTR
                                + kc + (((lane >> 3) & 1) << 3))) << 1;
                uint32_t r0, r1, r2, r3;
                ldsm4(r0, r1, r2, r3, bb + PANELB + boff);
                bh[p * 2][0] = r0; bh[p * 2][1] = r1; bh[p * 2 + 1][0] = r2; bh[p * 2 + 1][1] = r3;
            }
#pragma unroll
            for (int mt = 0; mt < 4; ++mt) {
                const uint32_t aoff =
                    ((uint32_t)((wm * 64 + mt * 16 + (lane & 15)) * ASTR + kc + ((lane >> 4) << 3))) << 1;
                uint32_t ah[4];
                ldsm4(ah[0], ah[1], ah[2], ah[3], bb + aoff);
#pragma unroll
                for (int nt = 0; nt < 4; ++nt)
                    mma16816(acc[mt][nt], ah, bh[nt]);
            }
        }
    };

    const int steps = K >> 5;
    if (AMODE == 3) cpaA(0, 0); else loadA(0);
    cpaB(0, 0);
    CP_COMMIT();
    if (AMODE != 3) stsA(0);
    CP_WAIT0();
    __syncthreads();

    for (int s = 0; s < steps; ++s) {
        const int buf = s & 1, nbuf = buf ^ 1;
        const bool more = (s + 1 < steps);
        if (more) {
            if (AMODE == 3) cpaA(s + 1, nbuf); else loadA(s + 1);
            cpaB(s + 1, nbuf);
            CP_COMMIT();
        }
        domma(buf);
        if (more) {
            if (AMODE != 3) stsA(nbuf);
            CP_WAIT0();
            __syncthreads();
        }
    }

    // ---- epilogue ----
    const int r0base = m0 + wm * 64 + (lane >> 2);
    const int cbase  = n0 + wn * 32 + (lane & 3) * 2;
#pragma unroll
    for (int mt = 0; mt < 4; ++mt) {
#pragma unroll
        for (int nt = 0; nt < 4; ++nt) {
            const int cB = cbase + nt * 8;
            const float b0v = bias[cB], b1v = bias[cB + 1];
            float c0 = acc[mt][nt][0] + b0v, c1 = acc[mt][nt][1] + b1v;
            float c2 = acc[mt][nt][2] + b0v, c3 = acc[mt][nt][3] + b1v;
            if (RELU) {
                c0 = fmaxf(c0, 0.f); c1 = fmaxf(c1, 0.f);
                c2 = fmaxf(c2, 0.f); c3 = fmaxf(c3, 0.f);
            }
            const int gR0 = r0base + mt * 16, gR1 = gR0 + 8;
            if (OUTSPLIT == 0) {
                if (gR0 < M) *(float2*)(Cf + (size_t)gR0 * ldc + cB) = make_float2(c0, c1);
                if (gR1 < M) *(float2*)(Cf + (size_t)gR1 * ldc + cB) = make_float2(c2, c3);
            } else {
                if (gR0 < M) *(uint32_t*)(Chi + (size_t)gR0 * ldc + cB) = pack_h2(c0, c1);
                if (gR1 < M) *(uint32_t*)(Chi + (size_t)gR1 * ldc + cB) = pack_h2(c2, c3);
            }
        }
    }
}

// ---------------- weight prep ----------------
__global__ void cvt_weightT_kernel(const float* __restrict__ W, int K, int N,
                                   __half* __restrict__ o)
{
    int i = blockIdx.x * blockDim.x + threadIdx.x;
    if (i >= K * N) return;
    int k = i / N, n = i % N;
    o[(size_t)n * K + k] = __float2half_rn(W[i]);
}

// ---------------- glue ----------------
__global__ void init_h_kernel(const int* __restrict__ nodes, const float* __restrict__ embed)
{
    int i = blockIdx.x * blockDim.x + threadIdx.x;
    if (i >= N_TOTAL * D) return;
    int row = i >> 7, c = i & 127;
    g_h[i] = embed[nodes[row / WINDOW] * D + c];
}
__global__ void edge_idx_kernel(const int* __restrict__ ie)
{
    int e = blockIdx.x * blockDim.x + threadIdx.x;
    if (e >= NE) return;
    int tt = ie[e * 3 + 0], s = ie[e * 3 + 1], d2 = ie[e * 3 + 2];
    g_nidx[e] = tt * N_NODES + s;
    g_midx[e] = tt * N_NODES + d2;
}
__global__ void zero_cnt_kernel()
{
    int i = blockIdx.x * blockDim.x + threadIdx.x;
    if (i < N_TOTAL) g_cnt[i] = 0;
}
__global__ void count_kernel()
{
    int e = blockIdx.x * blockDim.x + threadIdx.x;
    if (e < NE) atomicAdd(&g_cnt[g_midx[e]], 1);
}
__global__ void zero_agg_kernel()
{
    int i = blockIdx.x * blockDim.x + threadIdx.x;
    if (i < N_TOTAL * D) g_agg[i] = 0.f;
}
__global__ void scatter_kernel()
{
    int i = blockIdx.x * blockDim.x + threadIdx.x;
    if (i >= NE * D) return;
    int e = i >> 7, c = i & 127;
    atomicAdd(&g_agg[g_midx[e] * D + c], g_m[i]);
}
__global__ void mean_kernel()
{
    int i = blockIdx.x * blockDim.x + threadIdx.x;
    if (i >= N_TOTAL * D) return;
    int r = i >> 7;
    int c = g_cnt[r];
    g_agg[i] = (c > 0) ? g_agg[i] / (float)c : 0.f;
}
__global__ void temp_agg_kernel()
{
    int i = blockIdx.x * blockDim.x + threadIdx.x;
    if (i >= N_TOTAL * D) return;
    int v = i >> 7, c = i & 127;
    float s = 0.f; int n = 0;
    if (v >= N_NODES) { s += g_m[(v - N_NODES) * D + c]; n++; }
    if (v < TEDGE)    { s += g_m[(TEDGE + v) * D + c];   n++; }
    g_agg[i] = s / (float)n;
}
__device__ __forceinline__ float sigmoidf(float x) { return 1.f / (1.f + expf(-x)); }
__global__ void gru_kernel()
{
    int i = blockIdx.x * blockDim.x + threadIdx.x;
    if (i >= N_TOTAL * D) return;
    int r = i >> 7, c = i & 127;
    const float* xg = g_xg + (size_t)r * 384;
    const float* hg = g_hg + (size_t)r * 384;
    float z  = sigmoidf(xg[c]       + hg[c]);
    float rr = sigmoidf(xg[128 + c] + hg[128 + c]);
    float hc = tanhf(xg[256 + c] + rr * hg[256 + c]);
    float h = g_h[i];
    g_h[i] = z * h + (1.f - z) * hc;
}
__global__ void logits_softmax_kernel(const float* __restrict__ W3,
                                      const float* __restrict__ b3,
                                      float* __restrict__ out)
{
    const int row = blockIdx.x;
    const int w = threadIdx.x >> 5, lane = threadIdx.x & 31;
    __shared__ float lg[10];
    float s = 0.f;
    for (int k = lane; k < 512; k += 32)
        s += g_x2[(size_t)row * 512 + k] * W3[k * 10 + w];
#pragma unroll
    for (int o = 16; o; o >>= 1) s += __shfl_down_sync(0xffffffff, s, o);
    if (lane == 0) lg[w] = s + b3[w];
    __syncthreads();
    if (threadIdx.x == 0) {
        float mx = lg[0];
#pragma unroll
        for (int c = 1; c < 10; ++c) mx = fmaxf(mx, lg[c]);
        float e[10], sum = 0.f;
#pragma unroll
        for (int c = 0; c < 10; ++c) { e[c] = expf(lg[c] - mx); sum += e[c]; }
#pragma unroll
        for (int c = 0; c < 10; ++c) out[row * 10 + c] = e[c] / sum;
    }
}

// ---------------- host ----------------
extern "C" void kernel_launch(void* const* d_in, const int* in_sizes, int n_in,
                              void* d_out, int out_size)
{
    const int*   ie        = (const int*)  d_in[0];
    const int*   nodes     = (const int*)  d_in[1];
    const float* embed     = (const float*)d_in[2];
    const float* msg_W1    = (const float*)d_in[3];
    const float* msg_b1    = (const float*)d_in[4];
    const float* msg_W2    = (const float*)d_in[5];
    const float* msg_b2    = (const float*)d_in[6];
    const float* gru_int_W = (const float*)d_in[7];
    const float* gru_int_U = (const float*)d_in[8];
    const float* gru_int_b = (const float*)d_in[9];
    const float* gru_tmp_W = (const float*)d_in[10];
    const float* gru_tmp_U = (const float*)d_in[11];
    const float* gru_tmp_b = (const float*)d_in[12];
    const float* ro_W1     = (const float*)d_in[13];
    const float* ro_b1     = (const float*)d_in[14];
    const float* ro_W2     = (const float*)d_in[15];
    const float* ro_b2     = (const float*)d_in[16];
    const float* ro_W3     = (const float*)d_in[17];
    const float* ro_b3     = (const float*)d_in[18];
    float* out = (float*)d_out;

    float *h_p, *m_p, *agg_p, *xg_p, *hg_p, *x2_p, *P_p, *Q_p, *zero_p;
    int *nidx_p, *midx_p;
    __half *hid_p;
    __half *w1, *w2, *gi, *gu, *gt, *gv, *r1, *r2;
    cudaGetSymbolAddress((void**)&h_p, g_h);
    cudaGetSymbolAddress((void**)&m_p, g_m);
    cudaGetSymbolAddress((void**)&agg_p, g_agg);
    cudaGetSymbolAddress((void**)&xg_p, g_xg);
    cudaGetSymbolAddress((void**)&hg_p, g_hg);
    cudaGetSymbolAddress((void**)&x2_p, g_x2);
    cudaGetSymbolAddress((void**)&P_p, g_P);
    cudaGetSymbolAddress((void**)&Q_p, g_Q);
    cudaGetSymbolAddress((void**)&zero_p, g_zero1024);
    cudaGetSymbolAddress((void**)&nidx_p, g_nidx);
    cudaGetSymbolAddress((void**)&midx_p, g_midx);
    cudaGetSymbolAddress((void**)&hid_p, g_hid);
    cudaGetSymbolAddress((void**)&w1, g_W1t);
    cudaGetSymbolAddress((void**)&w2, g_W2t);
    cudaGetSymbolAddress((void**)&gi, g_GiW);
    cudaGetSymbolAddress((void**)&gu, g_GiU);
    cudaGetSymbolAddress((void**)&gt, g_GtW);
    cudaGetSymbolAddress((void**)&gv, g_GtU);
    cudaGetSymbolAddress((void**)&r1, g_R1t);
    cudaGetSymbolAddress((void**)&r2, g_R2t);

    cudaFuncSetAttribute(hmma_gemm<0,0,0>, cudaFuncAttributeMaxDynamicSharedMemorySize, SMEM_BYTES);
    cudaFuncSetAttribute(hmma_gemm<0,1,1>, cudaFuncAttributeMaxDynamicSharedMemorySize, SMEM_BYTES);
    cudaFuncSetAttribute(hmma_gemm<3,0,1>, cudaFuncAttributeMaxDynamicSharedMemorySize, SMEM_BYTES);
    cudaFuncSetAttribute(hmma_gemm<4,0,1>, cudaFuncAttributeMaxDynamicSharedMemorySize, SMEM_BYTES);
    cudaFuncSetAttribute(hmma_gemm<5,0,1>, cudaFuncAttributeMaxDynamicSharedMemorySize, SMEM_BYTES);

    const int EL = 256;
    cvt_weightT_kernel<<<(256*HID + EL-1)/EL, EL>>>(msg_W1, 256, HID, w1);
    cvt_weightT_kernel<<<(HID*D   + EL-1)/EL, EL>>>(msg_W2, HID, D,   w2);
    cvt_weightT_kernel<<<(D*384   + EL-1)/EL, EL>>>(gru_int_W, D, 384, gi);
    cvt_weightT_kernel<<<(D*384   + EL-1)/EL, EL>>>(gru_int_U, D, 384, gu);
    cvt_weightT_kernel<<<(D*384   + EL-1)/EL, EL>>>(gru_tmp_W, D, 384, gt);
    cvt_weightT_kernel<<<(D*384   + EL-1)/EL, EL>>>(gru_tmp_U, D, 384, gv);
    cvt_weightT_kernel<<<(D*HID   + EL-1)/EL, EL>>>(ro_W1, D, HID, r1);
    cvt_weightT_kernel<<<(HID*512 + EL-1)/EL, EL>>>(ro_W2, HID, 512, r2);

    init_h_kernel<<<(N_TOTAL*D + EL-1)/EL, EL>>>(nodes, embed);
    edge_idx_kernel<<<(NE + EL-1)/EL, EL>>>(ie);
    zero_cnt_kernel<<<(N_TOTAL + EL-1)/EL, EL>>>();
    count_kernel<<<(NE + EL-1)/EL, EL>>>();

    const int MT_E = NE / 128;
    const int MT_T = (TE2 + 127) / 128;
    const int MT_N = (N_TOTAL + 127) / 128;
    const int MT_R = (N_NODES + 127) / 128;

    for (int it = 0; it < 2; ++it) {
        // ---- interaction stage ----
        hmma_gemm<0,0,0><<<dim3(8, MT_N), 256, SMEM_BYTES>>>(
            h_p, nullptr, nullptr, D, nullptr, nullptr,
            w1, 256, msg_b1, P_p, nullptr, HID, N_TOTAL, D);
        hmma_gemm<0,0,0><<<dim3(8, MT_N), 256, SMEM_BYTES>>>(
            h_p, nullptr, nullptr, D, nullptr, nullptr,
            w1 + 128, 256, zero_p, Q_p, nullptr, HID, N_TOTAL, D);
        hmma_gemm<4,0,1><<<dim3(1, MT_E), 256, SMEM_BYTES>>>(
            P_p, Q_p, nullptr, 0, nidx_p, midx_p,
            w2, HID, msg_b2, m_p, nullptr, D, NE, HID);
        zero_agg_kernel<<<(N_TOTAL*D + EL-1)/EL, EL>>>();
        scatter_kernel<<<(NE*D + EL-1)/EL, EL>>>();
        mean_kernel<<<(N_TOTAL*D + EL-1)/EL, EL>>>();
        hmma_gemm<0,0,0><<<dim3(3, MT_N), 256, SMEM_BYTES>>>(
            agg_p, nullptr, nullptr, D, nullptr, nullptr,
            gi, D, gru_int_b, xg_p, nullptr, 384, N_TOTAL, D);
        hmma_gemm<0,0,0><<<dim3(3, MT_N), 256, SMEM_BYTES>>>(
            h_p, nullptr, nullptr, D, nullptr, nullptr,
            gu, D, gru_int_b + 384, hg_p, nullptr, 384, N_TOTAL, D);
        gru_kernel<<<(N_TOTAL*D + EL-1)/EL, EL>>>();

        // ---- temporal stage ----
        hmma_gemm<0,0,0><<<dim3(8, MT_N), 256, SMEM_BYTES>>>(
            h_p, nullptr, nullptr, D, nullptr, nullptr,
            w1, 256, msg_b1, P_p, nullptr, HID, N_TOTAL, D);
        hmma_gemm<0,0,0><<<dim3(8, MT_N), 256, SMEM_BYTES>>>(
            h_p, nullptr, nullptr, D, nullptr, nullptr,
            w1 + 128, 256, zero_p, Q_p, nullptr, HID, N_TOTAL, D);
        hmma_gemm<5,0,1><<<dim3(1, MT_T), 256, SMEM_BYTES>>>(
            P_p, Q_p, nullptr, 0, nullptr, nullptr,
            w2, HID, msg_b2, m_p, nullptr, D, TE2, HID);
        temp_agg_kernel<<<(N_TOTAL*D + EL-1)/EL, EL>>>();
        hmma_gemm<0,0,0><<<dim3(3, MT_N), 256, SMEM_BYTES>>>(
            agg_p, nullptr, nullptr, D, nullptr, nullptr,
            gt, D, gru_tmp_b, xg_p, nullptr, 384, N_TOTAL, D);
        hmma_gemm<0,0,0><<<dim3(3, MT_N), 256, SMEM_BYTES>>>(
            h_p, nullptr, nullptr, D, nullptr, nullptr,
            gv, D, gru_tmp_b + 384, hg_p, nullptr, 384, N_TOTAL, D);
        gru_kernel<<<(N_TOTAL*D + EL-1)/EL, EL>>>();
    }

    // ---- readout ----
    hmma_gemm<0,1,1><<<dim3(8, MT_R), 256, SMEM_BYTES>>>(
        h_p, nullptr, nullptr, D, nullptr, nullptr,
        r1, D, ro_b1, nullptr, hid_p, HID, N_NODES, D);
    hmma_gemm<3,0,1><<<dim3(4, MT_R), 256, SMEM_BYTES>>>(
        nullptr, nullptr, hid_p, HID, nullptr, nullptr,
        r2, HID, ro_b2, x2_p, nullptr, 512, N_NODES, HID);
    logits_softmax_kernel<<<N_NODES, 320>>>(ro_W3, ro_b3, out);
}

// round 8
// speedup vs baseline: 4.8041x; 1.1822x over previous
#include <cuda_runtime.h>
#include <cuda_fp16.h>
#include <math.h>
#include <stdint.h>

#define D        128
#define N_NODES  5000
#define WINDOW   10
#define N_TOTAL  50000
#define NE       131072
#define HID      1024
#define TEDGE    45000
#define TE2      90000

// ---------------- device scratch ----------------
__device__ __align__(16) float g_h[N_TOTAL * D];
__device__ __align__(16) float g_agg[N_TOTAL * D];
__device__ int   g_cnt[N_TOTAL];
__device__ int   g_nidx[NE];
__device__ int   g_midx[NE];
__device__ __align__(16) float g_x2[N_NODES * 512];
__device__ __align__(16) float g_zero1024[1024];

// fp16 intermediates
__device__ __align__(16) __half g_P16[(size_t)N_TOTAL * HID];
__device__ __align__(16) __half g_Q16[(size_t)N_TOTAL * HID];
__device__ __align__(16) __half g_m16[(size_t)NE * D];
__device__ __align__(16) __half g_xg16[(size_t)N_TOTAL * 384];
__device__ __align__(16) __half g_hg16[(size_t)N_TOTAL * 384];
__device__ __align__(16) __half g_hid[(size_t)N_NODES * HID];

// transposed fp16 weights, layout [N][K]
__device__ __align__(16) __half g_W1t[HID * 256];
__device__ __align__(16) __half g_W2t[D * HID];
__device__ __align__(16) __half g_GiW[384 * D];
__device__ __align__(16) __half g_GiU[384 * D];
__device__ __align__(16) __half g_GtW[384 * D];
__device__ __align__(16) __half g_GtU[384 * D];
__device__ __align__(16) __half g_R1t[HID * D];
__device__ __align__(16) __half g_R2t[512 * HID];

// ---------------- helpers ----------------
__device__ __forceinline__ uint32_t smem_u32(const void* p) {
    uint32_t a;
    asm("{ .reg .u64 t; cvta.to.shared.u64 t, %1; cvt.u32.u64 %0, t; }" : "=r"(a) : "l"(p));
    return a;
}
__device__ __forceinline__ void ldsm4(uint32_t& r0, uint32_t& r1, uint32_t& r2, uint32_t& r3, uint32_t addr) {
    asm volatile("ldmatrix.sync.aligned.m8n8.x4.shared.b16 {%0,%1,%2,%3}, [%4];"
                 : "=r"(r0), "=r"(r1), "=r"(r2), "=r"(r3) : "r"(addr));
}
__device__ __forceinline__ void mma16816(float* c, const uint32_t* a, const uint32_t* b) {
    asm volatile("mma.sync.aligned.m16n8k16.row.col.f32.f16.f16.f32 "
                 "{%0,%1,%2,%3}, {%4,%5,%6,%7}, {%8,%9}, {%0,%1,%2,%3};"
                 : "+f"(c[0]), "+f"(c[1]), "+f"(c[2]), "+f"(c[3])
                 : "r"(a[0]), "r"(a[1]), "r"(a[2]), "r"(a[3]), "r"(b[0]), "r"(b[1]));
}
__device__ __forceinline__ void cp16(uint32_t saddr, const void* g) {
    asm volatile("cp.async.cg.shared.global [%0], [%1], 16;" :: "r"(saddr), "l"(g));
}
#define CP_COMMIT() asm volatile("cp.async.commit_group;" ::: "memory")
#define CP_WAIT0()  asm volatile("cp.async.wait_group 0;" ::: "memory")

__device__ __forceinline__ uint32_t pack_h2(float x, float y) {
    __half2 h = __floats2half2_rn(x, y);
    return *(uint32_t*)&h;
}
__device__ __forceinline__ uint32_t hadd2_relu(uint32_t a, uint32_t b) {
    __half2 s = __hadd2(*(__half2*)&a, *(__half2*)&b);
    __half2 z = __float2half2_rn(0.f);
    __half2 r = __hmax2(s, z);
    return *(uint32_t*)&r;
}
__device__ __forceinline__ uint32_t havg2(uint32_t a, uint32_t b) {
    __half2 s = __hadd2(*(__half2*)&a, *(__half2*)&b);
    __half2 hlf = __float2half2_rn(0.5f);
    __half2 r = __hmul2(s, hlf);
    return *(uint32_t*)&r;
}

// ---------------- fp16 HMMA GEMM, double-buffered ----------------
// AMODE 0: A fp32 row-major stride lda (convert on load)
// AMODE 3: A fp16 row-major stride lda (cp.async)
// AMODE 4: A[r,k] = relu(P16[nidx[r]][k] + Q16[midx[r]][k])   (fp16 path)
// AMODE 5: same with analytic temporal indices
// AMODE 6: A[r,k] = g_agg[r][k] / max(cnt[r],1)               (fused mean)
// AMODE 7: A[r,k] = temporal mean of g_m16 rows               (fused temp_agg)
// OUTSPLIT 0: fp32 to Cf; OUTSPLIT 1: fp16 to Chi.
#define ASTR   56
#define PANEL  (128 * ASTR)
#define PANELB (PANEL * 2)               // 14336 B
#define BUF_BYTES (2 * PANELB)           // 28672 (A, B)
#define SMEM_BYTES (2 * BUF_BYTES)       // 57344

template<int AMODE, int OUTSPLIT, int RELU>
__global__ __launch_bounds__(256, 2)
void hmma_gemm(const float* __restrict__ Af,
               const __half* __restrict__ Ph,
               const __half* __restrict__ Qh,
               const __half* __restrict__ Ah_g,
               int lda,
               const int* __restrict__ idxA, const int* __restrict__ idxB,
               const int* __restrict__ cnt,
               const __half* __restrict__ Bw,
               int ldb,
               const float* __restrict__ bias,
               float* __restrict__ Cf,
               __half* __restrict__ Chi,
               int ldc, int M, int K)
{
    extern __shared__ __half smbuf[];
    const uint32_t sbase = smem_u32(smbuf);

    const int t = threadIdx.x, lane = t & 31, w = t >> 5;
    const int wm = w >> 2, wn = w & 3;
    const int m0 = blockIdx.y * 128, n0 = blockIdx.x * 128;
    const int lrow = t >> 1, lhalf = t & 1;
    const uint32_t arow_off = ((uint32_t)(lrow * ASTR + lhalf * 16)) << 1;

    float acc[4][4][4];
#pragma unroll
    for (int i = 0; i < 4; ++i)
#pragma unroll
        for (int j = 0; j < 4; ++j)
#pragma unroll
            for (int q = 0; q < 4; ++q) acc[i][j][q] = 0.f;

    uint32_t rh[8];

    auto loadA = [&](int s) {
        if (AMODE == 3) return;
        const int k0 = s << 5;
        int gRow = m0 + lrow; if (gRow >= M) gRow = M - 1;
        const int koff = k0 + lhalf * 16;
        if (AMODE == 4 || AMODE == 5) {
            int n_, m_;
            if (AMODE == 4) { n_ = idxA[gRow]; m_ = idxB[gRow]; }
            else {
                if (gRow < TEDGE) { n_ = gRow;                   m_ = gRow + N_NODES; }
                else              { n_ = gRow - TEDGE + N_NODES; m_ = gRow - TEDGE;   }
            }
            const uint4* p = (const uint4*)(Ph + (size_t)n_ * HID + koff);
            const uint4* q = (const uint4*)(Qh + (size_t)m_ * HID + koff);
            uint4 p0 = p[0], p1 = p[1], q0 = q[0], q1 = q[1];
            rh[0] = hadd2_relu(p0.x, q0.x); rh[1] = hadd2_relu(p0.y, q0.y);
            rh[2] = hadd2_relu(p0.z, q0.z); rh[3] = hadd2_relu(p0.w, q0.w);
            rh[4] = hadd2_relu(p1.x, q1.x); rh[5] = hadd2_relu(p1.y, q1.y);
            rh[6] = hadd2_relu(p1.z, q1.z); rh[7] = hadd2_relu(p1.w, q1.w);
        } else if (AMODE == 7) {
            const int v = gRow;
            const bool has1 = (v >= N_NODES);   // fwd edge: msg row v - N_NODES
            const bool has2 = (v < TEDGE);      // bwd edge: msg row TEDGE + v
            uint4 a0 = make_uint4(0,0,0,0), a1 = a0, b0 = a0, b1 = a0;
            if (has1) {
                const uint4* r = (const uint4*)(Ah_g + (size_t)(v - N_NODES) * D + koff);
                a0 = r[0]; a1 = r[1];
            }
            if (has2) {
                const uint4* r = (const uint4*)(Ah_g + (size_t)(TEDGE + v) * D + koff);
                b0 = r[0]; b1 = r[1];
            }
            if (has1 && has2) {
                rh[0] = havg2(a0.x, b0.x); rh[1] = havg2(a0.y, b0.y);
                rh[2] = havg2(a0.z, b0.z); rh[3] = havg2(a0.w, b0.w);
                rh[4] = havg2(a1.x, b1.x); rh[5] = havg2(a1.y, b1.y);
                rh[6] = havg2(a1.z, b1.z); rh[7] = havg2(a1.w, b1.w);
            } else if (has1) {
                rh[0] = a0.x; rh[1] = a0.y; rh[2] = a0.z; rh[3] = a0.w;
                rh[4] = a1.x; rh[5] = a1.y; rh[6] = a1.z; rh[7] = a1.w;
            } else {
                rh[0] = b0.x; rh[1] = b0.y; rh[2] = b0.z; rh[3] = b0.w;
                rh[4] = b1.x; rh[5] = b1.y; rh[6] = b1.z; rh[7] = b1.w;
            }
        } else {   // AMODE 0 or 6: fp32 source
            const float* src = Af + (size_t)gRow * lda + koff;
            float scale = 1.f;
            if (AMODE == 6) {
                int c = cnt[gRow];
                scale = 1.f / (float)(c > 0 ? c : 1);
            }
            float vv[16];
#pragma unroll
            for (int i = 0; i < 16; i += 4) {
                float4 v = *(const float4*)(src + i);
                vv[i] = v.x * scale; vv[i+1] = v.y * scale;
                vv[i+2] = v.z * scale; vv[i+3] = v.w * scale;
            }
#pragma unroll
            for (int i = 0; i < 8; ++i) rh[i] = pack_h2(vv[2*i], vv[2*i+1]);
            return;
        }
    };
    auto stsA = [&](int buf) {
        if (AMODE == 3) return;
        __half* dh = smbuf + (size_t)buf * (BUF_BYTES / 2) + lrow * ASTR + lhalf * 16;
        *(uint4*)dh       = make_uint4(rh[0], rh[1], rh[2], rh[3]);
        *(uint4*)(dh + 8) = make_uint4(rh[4], rh[5], rh[6], rh[7]);
    };
    auto cpaA = [&](int s, int buf) {   // AMODE 3
        const int k0 = s << 5;
        int gRow = m0 + lrow; if (gRow >= M) gRow = M - 1;
        const size_t off = (size_t)gRow * lda + k0 + lhalf * 16;
        const uint32_t d = sbase + buf * BUF_BYTES + arow_off;
        cp16(d,      Ah_g + off);
        cp16(d + 16, Ah_g + off + 8);
    };
    auto cpaB = [&](int s, int buf) {
        const int k0 = s << 5;
        const size_t off = (size_t)(n0 + lrow) * ldb + k0 + lhalf * 16;
        const uint32_t d = sbase + buf * BUF_BYTES + PANELB + arow_off;
        cp16(d,      Bw + off);
        cp16(d + 16, Bw + off + 8);
    };
    auto domma = [&](int buf) {
        const uint32_t bb = sbase + buf * BUF_BYTES;
#pragma unroll
        for (int kk = 0; kk < 2; ++kk) {
            const int kc = kk * 16;
            uint32_t bh[4][2];
#pragma unroll
            for (int p = 0; p < 2; ++p) {
                const uint32_t boff =
                    ((uint32_t)((wn * 32 + p * 16 + ((lane >> 4) << 3) + (lane & 7)) * ASTR
                                + kc + (((lane >> 3) & 1) << 3))) << 1;
                uint32_t r0, r1, r2, r3;
                ldsm4(r0, r1, r2, r3, bb + PANELB + boff);
                bh[p * 2][0] = r0; bh[p * 2][1] = r1; bh[p * 2 + 1][0] = r2; bh[p * 2 + 1][1] = r3;
            }
#pragma unroll
            for (int mt = 0; mt < 4; ++mt) {
                const uint32_t aoff =
                    ((uint32_t)((wm * 64 + mt * 16 + (lane & 15)) * ASTR + kc + ((lane >> 4) << 3))) << 1;
                uint32_t ah[4];
                ldsm4(ah[0], ah[1], ah[2], ah[3], bb + aoff);
#pragma unroll
                for (int nt = 0; nt < 4; ++nt)
                    mma16816(acc[mt][nt], ah, bh[nt]);
            }
        }
    };

    const int steps = K >> 5;
    if (AMODE == 3) cpaA(0, 0); else loadA(0);
    cpaB(0, 0);
    CP_COMMIT();
    if (AMODE != 3) stsA(0);
    CP_WAIT0();
    __syncthreads();

    for (int s = 0; s < steps; ++s) {
        const int buf = s & 1, nbuf = buf ^ 1;
        const bool more = (s + 1 < steps);
        if (more) {
            if (AMODE == 3) cpaA(s + 1, nbuf); else loadA(s + 1);
            cpaB(s + 1, nbuf);
            CP_COMMIT();
        }
        domma(buf);
        if (more) {
            if (AMODE != 3) stsA(nbuf);
            CP_WAIT0();
            __syncthreads();
        }
    }

    // ---- epilogue ----
    const int r0base = m0 + wm * 64 + (lane >> 2);
    const int cbase  = n0 + wn * 32 + (lane & 3) * 2;
#pragma unroll
    for (int mt = 0; mt < 4; ++mt) {
#pragma unroll
        for (int nt = 0; nt < 4; ++nt) {
            const int cB = cbase + nt * 8;
            const float b0v = bias[cB], b1v = bias[cB + 1];
            float c0 = acc[mt][nt][0] + b0v, c1 = acc[mt][nt][1] + b1v;
            float c2 = acc[mt][nt][2] + b0v, c3 = acc[mt][nt][3] + b1v;
            if (RELU) {
                c0 = fmaxf(c0, 0.f); c1 = fmaxf(c1, 0.f);
                c2 = fmaxf(c2, 0.f); c3 = fmaxf(c3, 0.f);
            }
            const int gR0 = r0base + mt * 16, gR1 = gR0 + 8;
            if (OUTSPLIT == 0) {
                if (gR0 < M) *(float2*)(Cf + (size_t)gR0 * ldc + cB) = make_float2(c0, c1);
                if (gR1 < M) *(float2*)(Cf + (size_t)gR1 * ldc + cB) = make_float2(c2, c3);
            } else {
                if (gR0 < M) *(uint32_t*)(Chi + (size_t)gR0 * ldc + cB) = pack_h2(c0, c1);
                if (gR1 < M) *(uint32_t*)(Chi + (size_t)gR1 * ldc + cB) = pack_h2(c2, c3);
            }
        }
    }
}

// ---------------- weight prep ----------------
__global__ void cvt_weightT_kernel(const float* __restrict__ W, int K, int N,
                                   __half* __restrict__ o)
{
    int i = blockIdx.x * blockDim.x + threadIdx.x;
    if (i >= K * N) return;
    int k = i / N, n = i % N;
    o[(size_t)n * K + k] = __float2half_rn(W[i]);
}

// ---------------- glue ----------------
__global__ void init_h_kernel(const int* __restrict__ nodes, const float* __restrict__ embed)
{
    int i = blockIdx.x * blockDim.x + threadIdx.x;
    if (i >= N_TOTAL * D) return;
    int row = i >> 7, c = i & 127;
    g_h[i] = embed[nodes[row / WINDOW] * D + c];
}
__global__ void edge_idx_kernel(const int* __restrict__ ie)
{
    int e = blockIdx.x * blockDim.x + threadIdx.x;
    if (e >= NE) return;
    int tt = ie[e * 3 + 0], s = ie[e * 3 + 1], d2 = ie[e * 3 + 2];
    g_nidx[e] = tt * N_NODES + s;
    g_midx[e] = tt * N_NODES + d2;
}
__global__ void zero_cnt_kernel()
{
    int i = blockIdx.x * blockDim.x + threadIdx.x;
    if (i < N_TOTAL) g_cnt[i] = 0;
}
__global__ void count_kernel()
{
    int e = blockIdx.x * blockDim.x + threadIdx.x;
    if (e < NE) atomicAdd(&g_cnt[g_midx[e]], 1);
}
__global__ void zero_agg_kernel()
{
    int i = blockIdx.x * blockDim.x + threadIdx.x;
    if (i < N_TOTAL * D) g_agg[i] = 0.f;
}
__global__ void scatter_kernel()
{
    int i = blockIdx.x * blockDim.x + threadIdx.x;
    if (i >= NE * D) return;
    int e = i >> 7, c = i & 127;
    atomicAdd(&g_agg[g_midx[e] * D + c], __half2float(g_m16[i]));
}
__device__ __forceinline__ float sigmoidf(float x) { return 1.f / (1.f + expf(-x)); }
__global__ void gru_kernel()
{
    int i = blockIdx.x * blockDim.x + threadIdx.x;
    if (i >= N_TOTAL * D) return;
    int r = i >> 7, c = i & 127;
    const __half* xg = g_xg16 + (size_t)r * 384;
    const __half* hg = g_hg16 + (size_t)r * 384;
    float z  = sigmoidf(__half2float(xg[c])       + __half2float(hg[c]));
    float rr = sigmoidf(__half2float(xg[128 + c]) + __half2float(hg[128 + c]));
    float hc = tanhf(__half2float(xg[256 + c]) + rr * __half2float(hg[256 + c]));
    float h = g_h[i];
    g_h[i] = z * h + (1.f - z) * hc;
}
__global__ void logits_softmax_kernel(const float* __restrict__ W3,
                                      const float* __restrict__ b3,
                                      float* __restrict__ out)
{
    const int row = blockIdx.x;
    const int w = threadIdx.x >> 5, lane = threadIdx.x & 31;
    __shared__ float lg[10];
    float s = 0.f;
    for (int k = lane; k < 512; k += 32)
        s += g_x2[(size_t)row * 512 + k] * W3[k * 10 + w];
#pragma unroll
    for (int o = 16; o; o >>= 1) s += __shfl_down_sync(0xffffffff, s, o);
    if (lane == 0) lg[w] = s + b3[w];
    __syncthreads();
    if (threadIdx.x == 0) {
        float mx = lg[0];
#pragma unroll
        for (int c = 1; c < 10; ++c) mx = fmaxf(mx, lg[c]);
        float e[10], sum = 0.f;
#pragma unroll
        for (int c = 0; c < 10; ++c) { e[c] = expf(lg[c] - mx); sum += e[c]; }
#pragma unroll
        for (int c = 0; c < 10; ++c) out[row * 10 + c] = e[c] / sum;
    }
}

// ---------------- host ----------------
extern "C" void kernel_launch(void* const* d_in, const int* in_sizes, int n_in,
                              void* d_out, int out_size)
{
    const int*   ie        = (const int*)  d_in[0];
    const int*   nodes     = (const int*)  d_in[1];
    const float* embed     = (const float*)d_in[2];
    const float* msg_W1    = (const float*)d_in[3];
    const float* msg_b1    = (const float*)d_in[4];
    const float* msg_W2    = (const float*)d_in[5];
    const float* msg_b2    = (const float*)d_in[6];
    const float* gru_int_W = (const float*)d_in[7];
    const float* gru_int_U = (const float*)d_in[8];
    const float* gru_int_b = (const float*)d_in[9];
    const float* gru_tmp_W = (const float*)d_in[10];
    const float* gru_tmp_U = (const float*)d_in[11];
    const float* gru_tmp_b = (const float*)d_in[12];
    const float* ro_W1     = (const float*)d_in[13];
    const float* ro_b1     = (const float*)d_in[14];
    const float* ro_W2     = (const float*)d_in[15];
    const float* ro_b2     = (const float*)d_in[16];
    const float* ro_W3     = (const float*)d_in[17];
    const float* ro_b3     = (const float*)d_in[18];
    float* out = (float*)d_out;

    float *h_p, *agg_p, *x2_p, *zero_p;
    int *nidx_p, *midx_p, *cnt_p;
    __half *P_p, *Q_p, *m_p, *xg_p, *hg_p, *hid_p;
    __half *w1, *w2, *gi, *gu, *gt, *gv, *r1, *r2;
    cudaGetSymbolAddress((void**)&h_p, g_h);
    cudaGetSymbolAddress((void**)&agg_p, g_agg);
    cudaGetSymbolAddress((void**)&x2_p, g_x2);
    cudaGetSymbolAddress((void**)&zero_p, g_zero1024);
    cudaGetSymbolAddress((void**)&nidx_p, g_nidx);
    cudaGetSymbolAddress((void**)&midx_p, g_midx);
    cudaGetSymbolAddress((void**)&cnt_p, g_cnt);
    cudaGetSymbolAddress((void**)&P_p, g_P16);
    cudaGetSymbolAddress((void**)&Q_p, g_Q16);
    cudaGetSymbolAddress((void**)&m_p, g_m16);
    cudaGetSymbolAddress((void**)&xg_p, g_xg16);
    cudaGetSymbolAddress((void**)&hg_p, g_hg16);
    cudaGetSymbolAddress((void**)&hid_p, g_hid);
    cudaGetSymbolAddress((void**)&w1, g_W1t);
    cudaGetSymbolAddress((void**)&w2, g_W2t);
    cudaGetSymbolAddress((void**)&gi, g_GiW);
    cudaGetSymbolAddress((void**)&gu, g_GiU);
    cudaGetSymbolAddress((void**)&gt, g_GtW);
    cudaGetSymbolAddress((void**)&gv, g_GtU);
    cudaGetSymbolAddress((void**)&r1, g_R1t);
    cudaGetSymbolAddress((void**)&r2, g_R2t);

    cudaFuncSetAttribute(hmma_gemm<0,1,0>, cudaFuncAttributeMaxDynamicSharedMemorySize, SMEM_BYTES);
    cudaFuncSetAttribute(hmma_gemm<0,1,1>, cudaFuncAttributeMaxDynamicSharedMemorySize, SMEM_BYTES);
    cudaFuncSetAttribute(hmma_gemm<3,0,1>, cudaFuncAttributeMaxDynamicSharedMemorySize, SMEM_BYTES);
    cudaFuncSetAttribute(hmma_gemm<4,1,1>, cudaFuncAttributeMaxDynamicSharedMemorySize, SMEM_BYTES);
    cudaFuncSetAttribute(hmma_gemm<5,1,1>, cudaFuncAttributeMaxDynamicSharedMemorySize, SMEM_BYTES);
    cudaFuncSetAttribute(hmma_gemm<6,1,0>, cudaFuncAttributeMaxDynamicSharedMemorySize, SMEM_BYTES);
    cudaFuncSetAttribute(hmma_gemm<7,1,0>, cudaFuncAttributeMaxDynamicSharedMemorySize, SMEM_BYTES);

    const int EL = 256;
    cvt_weightT_kernel<<<(256*HID + EL-1)/EL, EL>>>(msg_W1, 256, HID, w1);
    cvt_weightT_kernel<<<(HID*D   + EL-1)/EL, EL>>>(msg_W2, HID, D,   w2);
    cvt_weightT_kernel<<<(D*384   + EL-1)/EL, EL>>>(gru_int_W, D, 384, gi);
    cvt_weightT_kernel<<<(D*384   + EL-1)/EL, EL>>>(gru_int_U, D, 384, gu);
    cvt_weightT_kernel<<<(D*384   + EL-1)/EL, EL>>>(gru_tmp_W, D, 384, gt);
    cvt_weightT_kernel<<<(D*384   + EL-1)/EL, EL>>>(gru_tmp_U, D, 384, gv);
    cvt_weightT_kernel<<<(D*HID   + EL-1)/EL, EL>>>(ro_W1, D, HID, r1);
    cvt_weightT_kernel<<<(HID*512 + EL-1)/EL, EL>>>(ro_W2, HID, 512, r2);

    init_h_kernel<<<(N_TOTAL*D + EL-1)/EL, EL>>>(nodes, embed);
    edge_idx_kernel<<<(NE + EL-1)/EL, EL>>>(ie);
    zero_cnt_kernel<<<(N_TOTAL + EL-1)/EL, EL>>>();
    count_kernel<<<(NE + EL-1)/EL, EL>>>();

    const int MT_E = NE / 128;
    const int MT_T = (TE2 + 127) / 128;
    const int MT_N = (N_TOTAL + 127) / 128;
    const int MT_R = (N_NODES + 127) / 128;

    for (int it = 0; it < 2; ++it) {
        // ---- interaction stage ----
        hmma_gemm<0,1,0><<<dim3(8, MT_N), 256, SMEM_BYTES>>>(
            h_p, nullptr, nullptr, nullptr, D, nullptr, nullptr, nullptr,
            w1, 256, msg_b1, nullptr, P_p, HID, N_TOTAL, D);
        hmma_gemm<0,1,0><<<dim3(8, MT_N), 256, SMEM_BYTES>>>(
            h_p, nullptr, nullptr, nullptr, D, nullptr, nullptr, nullptr,
            w1 + 128, 256, zero_p, nullptr, Q_p, HID, N_TOTAL, D);
        hmma_gemm<4,1,1><<<dim3(1, MT_E), 256, SMEM_BYTES>>>(
            nullptr, P_p, Q_p, nullptr, 0, nidx_p, midx_p, nullptr,
            w2, HID, msg_b2, nullptr, m_p, D, NE, HID);
        zero_agg_kernel<<<(N_TOTAL*D + EL-1)/EL, EL>>>();
        scatter_kernel<<<(NE*D + EL-1)/EL, EL>>>();
        hmma_gemm<6,1,0><<<dim3(3, MT_N), 256, SMEM_BYTES>>>(
            agg_p, nullptr, nullptr, nullptr, D, nullptr, nullptr, cnt_p,
            gi, D, gru_int_b, nullptr, xg_p, 384, N_TOTAL, D);
        hmma_gemm<0,1,0><<<dim3(3, MT_N), 256, SMEM_BYTES>>>(
            h_p, nullptr, nullptr, nullptr, D, nullptr, nullptr, nullptr,
            gu, D, gru_int_b + 384, nullptr, hg_p, 384, N_TOTAL, D);
        gru_kernel<<<(N_TOTAL*D + EL-1)/EL, EL>>>();

        // ---- temporal stage ----
        hmma_gemm<0,1,0><<<dim3(8, MT_N), 256, SMEM_BYTES>>>(
            h_p, nullptr, nullptr, nullptr, D, nullptr, nullptr, nullptr,
            w1, 256, msg_b1, nullptr, P_p, HID, N_TOTAL, D);
        hmma_gemm<0,1,0><<<dim3(8, MT_N), 256, SMEM_BYTES>>>(
            h_p, nullptr, nullptr, nullptr, D, nullptr, nullptr, nullptr,
            w1 + 128, 256, zero_p, nullptr, Q_p, HID, N_TOTAL, D);
        hmma_gemm<5,1,1><<<dim3(1, MT_T), 256, SMEM_BYTES>>>(
            nullptr, P_p, Q_p, nullptr, 0, nullptr, nullptr, nullptr,
            w2, HID, msg_b2, nullptr, m_p, D, TE2, HID);
        hmma_gemm<7,1,0><<<dim3(3, MT_N), 256, SMEM_BYTES>>>(
            nullptr, nullptr, nullptr, m_p, D, nullptr, nullptr, nullptr,
            gt, D, gru_tmp_b, nullptr, xg_p, 384, N_TOTAL, D);
        hmma_gemm<0,1,0><<<dim3(3, MT_N), 256, SMEM_BYTES>>>(
            h_p, nullptr, nullptr, nullptr, D, nullptr, nullptr, nullptr,
            gv, D, gru_tmp_b + 384, nullptr, hg_p, 384, N_TOTAL, D);
        gru_kernel<<<(N_TOTAL*D + EL-1)/EL, EL>>>();
    }

    // ---- readout ----
    hmma_gemm<0,1,1><<<dim3(8, MT_R), 256, SMEM_BYTES>>>(
        h_p, nullptr, nullptr, nullptr, D, nullptr, nullptr, nullptr,
        r1, D, ro_b1, nullptr, hid_p, HID, N_NODES, D);
    hmma_gemm<3,0,1><<<dim3(4, MT_R), 256, SMEM_BYTES>>>(
        nullptr, nullptr, nullptr, hid_p, HID, nullptr, nullptr, nullptr,
        r2, HID, ro_b2, x2_p, nullptr, 512, N_NODES, HID);
    logits_softmax_kernel<<<N_NODES, 320>>>(ro_W3, ro_b3, out);
}